// round 6
// baseline (speedup 1.0000x reference)
#include <cuda_runtime.h>
#include <math.h>

typedef unsigned long long ULL;
typedef unsigned int U32;

#define NB 2
#define NS 2048
#define NE 1024
#define NH 16
#define NHD 64
#define NM 4096                  // NB*NS
#define ATT_SCALE (1.0f/32.0f)   // 1/sqrt(1024), exact power of two

// ---------------- scratch (device globals; no allocation allowed) ----------
__device__ float g_q[NB*NH*NS*NHD];    // head-major: [b*16+h][s][hd]
__device__ float g_k[NB*NH*NS*NHD];
__device__ float g_v[NB*NH*NS*NHD];
__device__ float g_ctx[NB*NH*NS*NHD];
__device__ float g_cos[NS*32];
__device__ float g_sin[NS*32];

// ---------------- tf32 mma.sync helpers (works on plain sm_103) ------------
__device__ __forceinline__ U32 f2tf(float x){
    U32 u; asm("cvt.rn.tf32.f32 %0, %1;" : "=r"(u) : "f"(x)); return u;
}
__device__ __forceinline__ void mma8(float* c, const U32* a, const U32* b){
    asm volatile("mma.sync.aligned.m16n8k8.row.col.f32.tf32.tf32.f32 "
        "{%0,%1,%2,%3}, {%4,%5,%6,%7}, {%8,%9}, {%0,%1,%2,%3};"
        : "+f"(c[0]), "+f"(c[1]), "+f"(c[2]), "+f"(c[3])
        : "r"(a[0]), "r"(a[1]), "r"(a[2]), "r"(a[3]), "r"(b[0]), "r"(b[1]));
}

// ============================================================================
// Projection GEMM, warp-tile 64x64, permuted+swizzled smem, double-buffered.
// C[m,n] = sum_e A[m,e]*W[n,e].  M=4096, N=1024, K=1024.
// CTA 128x128, 128 thr = 4 warps (2x2 of 64x64), BK=32.
//
// A-perm: group(ks,mf,grp,tig) -> 4 words {A[mf*16+grp][ks*8+tig],
//   A[+8][tig], A[grp][tig+4], A[+8][tig+4]}  == mma a0..a3 order.
//   byte = ks*4096 + mf*512 + grp*64 + (tig^((grp>>1)&3))*16 + khi*8 + hi*4
// B-perm: group(ks,nf,grp,tig) -> 2 words {B[nf*8+grp][ks*8+tig], [+4]}.
//   byte = ks*4096 + nf*256 + grp*32 + (tig^(((grp>>2)&1)|((nf&1)<<1)))*8 + khi*4
// ============================================================================
#define GWS_STAGE 32768          // bytes per stage: A 16K + B 16K
#define GWS_SMEM  (2*GWS_STAGE)  // 64 KB

__global__ void __launch_bounds__(128)
gemm_ws(const float* __restrict__ A, const float* __restrict__ Wt,
        float* __restrict__ C, int a_heads, int c_heads, int do_rope)
{
    extern __shared__ __align__(16) char smem[];
    const int t    = threadIdx.x;
    const int lane = t & 31;
    const int wid  = t >> 5;
    const int grp  = lane >> 2;          // 0..7
    const int tig  = lane & 3;           // 0..3
    const int wm   = (wid & 1) * 64;
    const int wn   = (wid >> 1) * 64;
    const int bm   = blockIdx.y * 128;
    const int bn   = blockIdx.x * 128;

    // producer-side constants (thread owns A-row t and B-row t)
    const int row  = t;
    const int mfA  = row >> 4, gA = row & 7, hiA = (row >> 3) & 1;
    const int swSA = (gA >> 1) & 3;
    const int nfB  = row >> 3, gB = row & 7;
    const int swSB = ((gB >> 2) & 1) | ((nfB & 1) << 1);

    // consumer-side constants
    const int tigA = tig ^ ((grp >> 1) & 3);
    const int sbgl = (grp >> 2) & 1;

    float acc[4][8][4];
    #pragma unroll
    for (int i=0;i<4;++i)
        #pragma unroll
        for (int j=0;j<8;++j)
            #pragma unroll
            for (int r=0;r<4;++r) acc[i][j][r] = 0.0f;

    float4 av[8], bv[8];

    auto LDG = [&](int kt){
        const int k0 = kt * 32;
        const float* pa;
        if (!a_heads) pa = A + (size_t)(bm + row)*NE + k0;
        else {
            int m = bm + row, b = m >> 11, s = m & 2047;
            pa = A + ((size_t)((b*16 + (k0 >> 6))*NS + s))*64 + (k0 & 63);
        }
        const float* pb = Wt + (size_t)(bn + row)*NE + k0;
        #pragma unroll
        for (int i = 0; i < 8; ++i) {
            av[i] = *(const float4*)(pa + i*4);
            bv[i] = *(const float4*)(pb + i*4);
        }
    };

    auto STS = [&](int st){
        char* sA = smem + st*GWS_STAGE;
        char* sB = sA + 16384;
        const float* afl = (const float*)av;
        const float* bfl = (const float*)bv;
        #pragma unroll
        for (int k = 0; k < 32; ++k) {
            int ks = k >> 3, tg = k & 3, khi = (k >> 2) & 1;
            *(U32*)(sA + ks*4096 + mfA*512 + gA*64
                        + ((tg ^ swSA) << 4) + khi*8 + hiA*4) = f2tf(afl[k]);
            *(U32*)(sB + ks*4096 + nfB*256 + gB*32
                        + ((tg ^ swSB) << 3) + khi*4) = f2tf(bfl[k]);
        }
    };

    auto MMA = [&](int st){
        char* sA = smem + st*GWS_STAGE;
        char* sB = sA + 16384;
        #pragma unroll
        for (int ks = 0; ks < 4; ++ks) {
            uint4 af[4];
            #pragma unroll
            for (int mf = 0; mf < 4; ++mf) {
                int mfi = (wm >> 4) + mf;
                af[mf] = *(const uint4*)(sA + ks*4096 + mfi*512 + grp*64 + (tigA << 4));
            }
            uint2 bf[8];
            #pragma unroll
            for (int nf = 0; nf < 8; ++nf) {
                int nfi = (wn >> 3) + nf;
                int tb  = tig ^ (sbgl | ((nfi & 1) << 1));
                bf[nf]  = *(const uint2*)(sB + ks*4096 + nfi*256 + grp*32 + (tb << 3));
            }
            #pragma unroll
            for (int mf = 0; mf < 4; ++mf)
                #pragma unroll
                for (int nf = 0; nf < 8; ++nf)
                    mma8(acc[mf][nf], (const U32*)&af[mf], (const U32*)&bf[nf]);
        }
    };

    LDG(0); STS(0); __syncthreads();
    for (int kt = 0; kt < 32; ++kt) {
        if (kt < 31) LDG(kt + 1);        // in flight during mma
        MMA(kt & 1);
        __syncthreads();
        if (kt < 31) { STS((kt + 1) & 1); __syncthreads(); }
    }

    // epilogue (+ optional fused RoPE: each float2 = one (even,odd) hd pair)
    #pragma unroll
    for (int mf = 0; mf < 4; ++mf) {
        #pragma unroll
        for (int half = 0; half < 2; ++half) {
            int m = bm + wm + mf*16 + grp + half*8;
            #pragma unroll
            for (int nf = 0; nf < 8; ++nf) {
                int n = bn + wn + nf*8 + 2*tig;
                float fx = acc[mf][nf][half*2 + 0];
                float fy = acc[mf][nf][half*2 + 1];
                if (do_rope) {
                    int s = m & 2047;
                    int p = (n & 63) >> 1;
                    float co = g_cos[s*32 + p], sn = g_sin[s*32 + p];
                    float rx = fx*co - fy*sn;
                    float ry = fx*sn + fy*co;
                    fx = rx; fy = ry;
                }
                float2 f = make_float2(fx, fy);
                if (!c_heads) {
                    *(float2*)(C + (size_t)m*NE + n) = f;
                } else {
                    int b = m >> 11, s2 = m & 2047;
                    *(float2*)(C + ((size_t)((b*16 + (n>>6))*NS + s2))*64 + (n & 63)) = f;
                }
            }
        }
    }
}

// ---------------- RoPE table -----------------------------------------------
__global__ void rope_table_kernel()
{
    int idx = blockIdx.x * blockDim.x + threadIdx.x;   // 65536
    if (idx >= NS*32) return;
    int s = idx >> 5, p = idx & 31;
    double invf = 1.0 / pow(10000.0, (double)(2*p) / 64.0);
    double a = (double)s * invf;
    g_cos[idx] = (float)cos(a);
    g_sin[idx] = (float)sin(a);
}

// ---------------- Flash attention with tf32 mma.sync (unchanged, R5) -------
#define FSW 72
#define FL_BYTES (4*64*FSW*4)      // Qs, Ks, Vs, Ps = 73728 B

__global__ void __launch_bounds__(128)
flash_mma_kernel()
{
    extern __shared__ __align__(16) U32 sm[];
    U32* Qs = sm;                  // [d][r]  (Q^T, pre-scaled, tf32)
    U32* Ks = sm + 64*FSW;         // [d][c]  (K^T, tf32)
    U32* Vs = sm + 2*64*FSW;       // [c][d]  (tf32)
    U32* Ps = sm + 3*64*FSW;       // [c][r]  (P^T, tf32)

    const int t    = threadIdx.x;
    const int lane = t & 31;
    const int wid  = t >> 5;
    const int grp  = lane >> 2;          // 0..7
    const int tig  = lane & 3;           // 0..3
    const int wr   = wid * 16;           // warp's q-row base within tile
    const int bh   = blockIdx.y;
    const int qb   = (int)gridDim.x - 1 - (int)blockIdx.x;  // heavy first
    const int q0   = qb * 64;

    const float* qp = g_q + (size_t)bh * NS * 64;
    const float* kp = g_k + (size_t)bh * NS * 64;
    const float* vp = g_v + (size_t)bh * NS * 64;

    #pragma unroll
    for (int it = 0; it < 8; ++it) {
        int i4  = it*128 + t;            // 1024 float4
        int row = i4 >> 4, c4 = i4 & 15;
        float4 f = *(const float4*)(qp + (size_t)(q0+row)*64 + c4*4);
        int d = c4*4;
        Qs[(d+0)*FSW + row] = f2tf(f.x * ATT_SCALE);
        Qs[(d+1)*FSW + row] = f2tf(f.y * ATT_SCALE);
        Qs[(d+2)*FSW + row] = f2tf(f.z * ATT_SCALE);
        Qs[(d+3)*FSW + row] = f2tf(f.w * ATT_SCALE);
    }

    float m_[2], l_[2];
    m_[0] = m_[1] = -1e30f;
    l_[0] = l_[1] = 0.0f;
    float octx[8][4];
    #pragma unroll
    for (int nf=0;nf<8;++nf)
        #pragma unroll
        for (int r=0;r<4;++r) octx[nf][r] = 0.0f;

    for (int kb = 0; kb <= qb; ++kb) {
        const int k0 = kb * 64;
        if (kb) __syncthreads();
        #pragma unroll
        for (int it = 0; it < 8; ++it) {
            int i4  = it*128 + t;
            int row = i4 >> 4, c4 = i4 & 15;
            float4 f = *(const float4*)(kp + (size_t)(k0+row)*64 + c4*4);
            int d = c4*4;
            Ks[(d+0)*FSW + row] = f2tf(f.x);
            Ks[(d+1)*FSW + row] = f2tf(f.y);
            Ks[(d+2)*FSW + row] = f2tf(f.z);
            Ks[(d+3)*FSW + row] = f2tf(f.w);
            float4 g = *(const float4*)(vp + (size_t)(k0+row)*64 + c4*4);
            uint4 u;
            u.x=f2tf(g.x); u.y=f2tf(g.y); u.z=f2tf(g.z); u.w=f2tf(g.w);
            *(uint4*)(&Vs[row*FSW + d]) = u;
        }
        __syncthreads();

        float sacc[8][4];
        #pragma unroll
        for (int nf=0;nf<8;++nf)
            #pragma unroll
            for (int r=0;r<4;++r) sacc[nf][r] = 0.0f;
        #pragma unroll
        for (int ks = 0; ks < 8; ++ks) {
            const int kk = ks * 8;
            U32 af[4];
            af[0] = Qs[(kk + tig    )*FSW + wr + grp    ];
            af[1] = Qs[(kk + tig    )*FSW + wr + grp + 8];
            af[2] = Qs[(kk + tig + 4)*FSW + wr + grp    ];
            af[3] = Qs[(kk + tig + 4)*FSW + wr + grp + 8];
            #pragma unroll
            for (int nf = 0; nf < 8; ++nf) {
                U32 bf[2];
                bf[0] = Ks[(kk + tig    )*FSW + nf*8 + grp];
                bf[1] = Ks[(kk + tig + 4)*FSW + nf*8 + grp];
                mma8(sacc[nf], af, bf);
            }
        }

        const bool diag = (kb == qb);
        #pragma unroll
        for (int l = 0; l < 2; ++l) {
            const int rloc = wr + grp + 8*l;
            const int gi   = q0 + rloc;
            float rm = -1e30f;
            #pragma unroll
            for (int nf = 0; nf < 8; ++nf) {
                #pragma unroll
                for (int c = 0; c < 2; ++c) {
                    float s = sacc[nf][2*l + c];
                    if (diag) {
                        int gj = k0 + nf*8 + 2*tig + c;
                        if (gj >= gi && !(gi == 0 && gj == 0)) s = -1e30f;
                    }
                    sacc[nf][2*l + c] = s;
                    rm = fmaxf(rm, s);
                }
            }
            rm = fmaxf(rm, __shfl_xor_sync(0xffffffffu, rm, 1));
            rm = fmaxf(rm, __shfl_xor_sync(0xffffffffu, rm, 2));
            float mnew = fmaxf(m_[l], rm);
            float fac  = __expf(m_[l] - mnew);
            float ps = 0.0f;
            #pragma unroll
            for (int nf = 0; nf < 8; ++nf) {
                #pragma unroll
                for (int c = 0; c < 2; ++c) {
                    float p = __expf(sacc[nf][2*l + c] - mnew);
                    Ps[(nf*8 + 2*tig + c)*FSW + rloc] = f2tf(p);
                    ps += p;
                }
            }
            ps += __shfl_xor_sync(0xffffffffu, ps, 1);
            ps += __shfl_xor_sync(0xffffffffu, ps, 2);
            l_[l] = l_[l]*fac + ps;
            m_[l] = mnew;
            #pragma unroll
            for (int nf = 0; nf < 8; ++nf) {
                octx[nf][2*l + 0] *= fac;
                octx[nf][2*l + 1] *= fac;
            }
        }
        __syncwarp();

        #pragma unroll
        for (int ks = 0; ks < 8; ++ks) {
            const int kk = ks * 8;
            U32 af[4];
            af[0] = Ps[(kk + tig    )*FSW + wr + grp    ];
            af[1] = Ps[(kk + tig    )*FSW + wr + grp + 8];
            af[2] = Ps[(kk + tig + 4)*FSW + wr + grp    ];
            af[3] = Ps[(kk + tig + 4)*FSW + wr + grp + 8];
            #pragma unroll
            for (int nf = 0; nf < 8; ++nf) {
                U32 bf[2];
                bf[0] = Vs[(kk + tig    )*FSW + nf*8 + grp];
                bf[1] = Vs[(kk + tig + 4)*FSW + nf*8 + grp];
                mma8(octx[nf], af, bf);
            }
        }
    }

    float* op = g_ctx + (size_t)bh * NS * 64;
    #pragma unroll
    for (int l = 0; l < 2; ++l) {
        const int r  = q0 + wr + grp + 8*l;
        const float inv = 1.0f / l_[l];
        #pragma unroll
        for (int nf = 0; nf < 8; ++nf) {
            float2 f;
            f.x = octx[nf][2*l + 0] * inv;
            f.y = octx[nf][2*l + 1] * inv;
            *(float2*)(op + (size_t)r*64 + nf*8 + 2*tig) = f;
        }
    }
}

// ---------------------------------------------------------------------------
extern "C" void kernel_launch(void* const* d_in, const int* in_sizes, int n_in,
                              void* d_out, int out_size)
{
    const float* q  = (const float*)d_in[0];
    const float* k  = (const float*)d_in[1];
    const float* v  = (const float*)d_in[2];
    const float* Wq = (const float*)d_in[3];
    const float* Wk = (const float*)d_in[4];
    const float* Wv = (const float*)d_in[5];
    const float* Wo = (const float*)d_in[6];
    float* out = (float*)d_out;

    float *pq, *pk, *pv, *pctx;
    cudaGetSymbolAddress((void**)&pq,   g_q);
    cudaGetSymbolAddress((void**)&pk,   g_k);
    cudaGetSymbolAddress((void**)&pv,   g_v);
    cudaGetSymbolAddress((void**)&pctx, g_ctx);

    cudaFuncSetAttribute(flash_mma_kernel,
                         cudaFuncAttributeMaxDynamicSharedMemorySize,
                         FL_BYTES);
    cudaFuncSetAttribute(gemm_ws,
                         cudaFuncAttributeMaxDynamicSharedMemorySize,
                         GWS_SMEM);

    rope_table_kernel<<<256, 256>>>();

    dim3 gg(NE/128, NM/128);               // (8, 32)
    gemm_ws<<<gg, 128, GWS_SMEM>>>(q, Wq, pq, 0, 1, 1);   // Q proj + RoPE
    gemm_ws<<<gg, 128, GWS_SMEM>>>(k, Wk, pk, 0, 1, 1);   // K proj + RoPE
    gemm_ws<<<gg, 128, GWS_SMEM>>>(v, Wv, pv, 0, 1, 0);   // V proj

    dim3 fg(NS/64, NB*NH);                 // (32, 32)
    flash_mma_kernel<<<fg, 128, FL_BYTES>>>();

    gemm_ws<<<gg, 128, GWS_SMEM>>>(pctx, Wo, out, 1, 0, 0);  // output proj
}

// round 7
// speedup vs baseline: 1.1530x; 1.1530x over previous
#include <cuda_runtime.h>
#include <math.h>

typedef unsigned long long ULL;
typedef unsigned int U32;

#define NB 2
#define NS 2048
#define NE 1024
#define NH 16
#define NHD 64
#define NM 4096                  // NB*NS
#define ATT_SCALE (1.0f/32.0f)   // 1/sqrt(1024), exact power of two

// ---------------- scratch (device globals; no allocation allowed) ----------
__device__ float g_q[NB*NH*NS*NHD];    // head-major: [b*16+h][s][hd]
__device__ float g_k[NB*NH*NS*NHD];
__device__ float g_v[NB*NH*NS*NHD];
__device__ float g_ctx[NB*NH*NS*NHD];
__device__ float g_cos[NS*32];
__device__ float g_sin[NS*32];

// ---------------- tf32 mma.sync helpers (works on plain sm_103) ------------
__device__ __forceinline__ U32 f2tf(float x){
    U32 u; asm("cvt.rn.tf32.f32 %0, %1;" : "=r"(u) : "f"(x)); return u;
}
__device__ __forceinline__ void mma8(float* c, const U32* a, const U32* b){
    asm volatile("mma.sync.aligned.m16n8k8.row.col.f32.tf32.tf32.f32 "
        "{%0,%1,%2,%3}, {%4,%5,%6,%7}, {%8,%9}, {%0,%1,%2,%3};"
        : "+f"(c[0]), "+f"(c[1]), "+f"(c[2]), "+f"(c[3])
        : "r"(a[0]), "r"(a[1]), "r"(a[2]), "r"(a[3]), "r"(b[0]), "r"(b[1]));
}

// ============================================================================
// Projection GEMM v3: 256 thr = 8 warps (2x4), warp tile 64x32, BK=16,
// permuted+swizzled smem (A-frag = LDS.128, B-frag = LDS.64, conflict-free),
// 2-stage double buffer, ONE __syncthreads per ktile.
//
// A-group(ks,mf,grp,tig) 16B = mma a0..a3 order:
//   byte = ks*4096 + mf*512 + grp*64 + (tig^((grp>>1)&3))*16 + khi*8 + hi*4
//   holds A[mf*16+grp+8*hi][ks*8+tig+4*khi]
// B-group(ks,nf,grp,tig) 8B:
//   byte = ks*4096 + nf*256 + grp*32 + (tig^(((grp>>2)&1)|((nf&1)<<1)))*8 + khi*4
//   holds B[nf*8+grp][ks*8+tig+4*khi]
// ============================================================================
#define GST 16384                // bytes per stage: A 8K + B 8K

__global__ void __launch_bounds__(256, 2)
gemm_mma(const float* __restrict__ A, const float* __restrict__ Wt,
         float* __restrict__ C, int a_heads, int c_heads, int do_rope)
{
    __shared__ __align__(16) char smem[2*GST];
    const int t    = threadIdx.x;
    const int lane = t & 31;
    const int wid  = t >> 5;
    const int grp  = lane >> 2;          // 0..7
    const int tig  = lane & 3;           // 0..3
    const int wm   = (wid & 1) * 64;
    const int wn   = (wid >> 1) * 32;
    const int bm   = blockIdx.y * 128;
    const int bn   = blockIdx.x * 128;

    // producer constants: thread owns A-row ar / B-row ar, k-half ksP
    const int ar   = t >> 1;             // 0..127
    const int ksP  = t & 1;              // which k-octet (BK=16 -> 2)
    const int mfA  = ar >> 4, gA = ar & 7, hiA = (ar >> 3) & 1;
    const int swSA = (gA >> 1) & 3;
    const int nfB  = ar >> 3, gB = ar & 7;
    const int swSB = ((gB >> 2) & 1) | ((nfB & 1) << 1);
    char* const pAa = smem + ksP*4096 + mfA*512 + gA*64 + hiA*4;
    char* const pBb = smem + 8192 + ksP*4096 + nfB*256 + gB*32;

    // consumer constants
    const int tigA = tig ^ ((grp >> 1) & 3);
    const int sbgl = (grp >> 2) & 1;

    float acc[4][4][4];
    #pragma unroll
    for (int i=0;i<4;++i)
        #pragma unroll
        for (int j=0;j<4;++j)
            #pragma unroll
            for (int r=0;r<4;++r) acc[i][j][r] = 0.0f;

    float4 av[2], bv[2];

    auto LDG = [&](int kt){
        const int e0 = kt*16 + ksP*8;
        const float* pa;
        if (!a_heads) pa = A + (size_t)(bm + ar)*NE + e0;
        else {
            int m = bm + ar, b = m >> 11, s = m & 2047;
            pa = A + ((size_t)((b*16 + (e0 >> 6))*NS + s))*64 + (e0 & 63);
        }
        const float* pb = Wt + (size_t)(bn + ar)*NE + e0;
        av[0] = *(const float4*)(pa);   av[1] = *(const float4*)(pa+4);
        bv[0] = *(const float4*)(pb);   bv[1] = *(const float4*)(pb+4);
    };

    auto STS = [&](int st){
        char* sA = pAa + st*GST;
        char* sB = pBb + st*GST;
        const float* afl = (const float*)av;
        const float* bfl = (const float*)bv;
        #pragma unroll
        for (int k = 0; k < 8; ++k) {
            int tg = k & 3, khi = (k >> 2) & 1;
            *(U32*)(sA + ((tg ^ swSA) << 4) + khi*8) = f2tf(afl[k]);
            *(U32*)(sB + ((tg ^ swSB) << 3) + khi*4) = f2tf(bfl[k]);
        }
    };

    auto MMA = [&](int st){
        char* sA = smem + st*GST;
        char* sB = sA + 8192;
        #pragma unroll
        for (int ks = 0; ks < 2; ++ks) {
            uint4 af[4];
            #pragma unroll
            for (int mf = 0; mf < 4; ++mf) {
                int mfi = (wm >> 4) + mf;
                af[mf] = *(const uint4*)(sA + ks*4096 + mfi*512 + grp*64 + (tigA << 4));
            }
            uint2 bf[4];
            #pragma unroll
            for (int nf = 0; nf < 4; ++nf) {
                int nfi = (wn >> 3) + nf;
                int tb  = tig ^ (sbgl | ((nfi & 1) << 1));
                bf[nf]  = *(const uint2*)(sB + ks*4096 + nfi*256 + grp*32 + (tb << 3));
            }
            #pragma unroll
            for (int mf = 0; mf < 4; ++mf)
                #pragma unroll
                for (int nf = 0; nf < 4; ++nf)
                    mma8(acc[mf][nf], (const U32*)&af[mf], (const U32*)&bf[nf]);
        }
    };

    LDG(0); STS(0); __syncthreads();
    for (int kt = 0; kt < 64; ++kt) {
        if (kt < 63) LDG(kt + 1);         // global loads in flight
        MMA(kt & 1);                      // covers LDG latency
        if (kt < 63) STS((kt + 1) & 1);   // opposite stage: no hazard
        __syncthreads();
    }

    // epilogue (+ optional fused RoPE: float2 = one (even,odd) hd pair)
    #pragma unroll
    for (int mf = 0; mf < 4; ++mf) {
        #pragma unroll
        for (int half = 0; half < 2; ++half) {
            int m = bm + wm + mf*16 + grp + half*8;
            #pragma unroll
            for (int nf = 0; nf < 4; ++nf) {
                int n = bn + wn + nf*8 + 2*tig;
                float fx = acc[mf][nf][half*2 + 0];
                float fy = acc[mf][nf][half*2 + 1];
                if (do_rope) {
                    int s = m & 2047;
                    int p = (n & 63) >> 1;
                    float co = g_cos[s*32 + p], sn = g_sin[s*32 + p];
                    float rx = fx*co - fy*sn;
                    float ry = fx*sn + fy*co;
                    fx = rx; fy = ry;
                }
                float2 f = make_float2(fx, fy);
                if (!c_heads) {
                    *(float2*)(C + (size_t)m*NE + n) = f;
                } else {
                    int b = m >> 11, s2 = m & 2047;
                    *(float2*)(C + ((size_t)((b*16 + (n>>6))*NS + s2))*64 + (n & 63)) = f;
                }
            }
        }
    }
}

// ---------------- RoPE table -----------------------------------------------
__global__ void rope_table_kernel()
{
    int idx = blockIdx.x * blockDim.x + threadIdx.x;   // 65536
    if (idx >= NS*32) return;
    int s = idx >> 5, p = idx & 31;
    double invf = 1.0 / pow(10000.0, (double)(2*p) / 64.0);
    double a = (double)s * invf;
    g_cos[idx] = (float)cos(a);
    g_sin[idx] = (float)sin(a);
}

// ---------------- Flash attention with tf32 mma.sync (unchanged, R5) -------
#define FSW 72
#define FL_BYTES (4*64*FSW*4)      // Qs, Ks, Vs, Ps = 73728 B

__global__ void __launch_bounds__(128)
flash_mma_kernel()
{
    extern __shared__ __align__(16) U32 sm[];
    U32* Qs = sm;                  // [d][r]  (Q^T, pre-scaled, tf32)
    U32* Ks = sm + 64*FSW;         // [d][c]  (K^T, tf32)
    U32* Vs = sm + 2*64*FSW;       // [c][d]  (tf32)
    U32* Ps = sm + 3*64*FSW;       // [c][r]  (P^T, tf32)

    const int t    = threadIdx.x;
    const int lane = t & 31;
    const int wid  = t >> 5;
    const int grp  = lane >> 2;          // 0..7
    const int tig  = lane & 3;           // 0..3
    const int wr   = wid * 16;           // warp's q-row base within tile
    const int bh   = blockIdx.y;
    const int qb   = (int)gridDim.x - 1 - (int)blockIdx.x;  // heavy first
    const int q0   = qb * 64;

    const float* qp = g_q + (size_t)bh * NS * 64;
    const float* kp = g_k + (size_t)bh * NS * 64;
    const float* vp = g_v + (size_t)bh * NS * 64;

    #pragma unroll
    for (int it = 0; it < 8; ++it) {
        int i4  = it*128 + t;            // 1024 float4
        int row = i4 >> 4, c4 = i4 & 15;
        float4 f = *(const float4*)(qp + (size_t)(q0+row)*64 + c4*4);
        int d = c4*4;
        Qs[(d+0)*FSW + row] = f2tf(f.x * ATT_SCALE);
        Qs[(d+1)*FSW + row] = f2tf(f.y * ATT_SCALE);
        Qs[(d+2)*FSW + row] = f2tf(f.z * ATT_SCALE);
        Qs[(d+3)*FSW + row] = f2tf(f.w * ATT_SCALE);
    }

    float m_[2], l_[2];
    m_[0] = m_[1] = -1e30f;
    l_[0] = l_[1] = 0.0f;
    float octx[8][4];
    #pragma unroll
    for (int nf=0;nf<8;++nf)
        #pragma unroll
        for (int r=0;r<4;++r) octx[nf][r] = 0.0f;

    for (int kb = 0; kb <= qb; ++kb) {
        const int k0 = kb * 64;
        if (kb) __syncthreads();
        #pragma unroll
        for (int it = 0; it < 8; ++it) {
            int i4  = it*128 + t;
            int row = i4 >> 4, c4 = i4 & 15;
            float4 f = *(const float4*)(kp + (size_t)(k0+row)*64 + c4*4);
            int d = c4*4;
            Ks[(d+0)*FSW + row] = f2tf(f.x);
            Ks[(d+1)*FSW + row] = f2tf(f.y);
            Ks[(d+2)*FSW + row] = f2tf(f.z);
            Ks[(d+3)*FSW + row] = f2tf(f.w);
            float4 g = *(const float4*)(vp + (size_t)(k0+row)*64 + c4*4);
            uint4 u;
            u.x=f2tf(g.x); u.y=f2tf(g.y); u.z=f2tf(g.z); u.w=f2tf(g.w);
            *(uint4*)(&Vs[row*FSW + d]) = u;
        }
        __syncthreads();

        float sacc[8][4];
        #pragma unroll
        for (int nf=0;nf<8;++nf)
            #pragma unroll
            for (int r=0;r<4;++r) sacc[nf][r] = 0.0f;
        #pragma unroll
        for (int ks = 0; ks < 8; ++ks) {
            const int kk = ks * 8;
            U32 af[4];
            af[0] = Qs[(kk + tig    )*FSW + wr + grp    ];
            af[1] = Qs[(kk + tig    )*FSW + wr + grp + 8];
            af[2] = Qs[(kk + tig + 4)*FSW + wr + grp    ];
            af[3] = Qs[(kk + tig + 4)*FSW + wr + grp + 8];
            #pragma unroll
            for (int nf = 0; nf < 8; ++nf) {
                U32 bf[2];
                bf[0] = Ks[(kk + tig    )*FSW + nf*8 + grp];
                bf[1] = Ks[(kk + tig + 4)*FSW + nf*8 + grp];
                mma8(sacc[nf], af, bf);
            }
        }

        const bool diag = (kb == qb);
        #pragma unroll
        for (int l = 0; l < 2; ++l) {
            const int rloc = wr + grp + 8*l;
            const int gi   = q0 + rloc;
            float rm = -1e30f;
            #pragma unroll
            for (int nf = 0; nf < 8; ++nf) {
                #pragma unroll
                for (int c = 0; c < 2; ++c) {
                    float s = sacc[nf][2*l + c];
                    if (diag) {
                        int gj = k0 + nf*8 + 2*tig + c;
                        if (gj >= gi && !(gi == 0 && gj == 0)) s = -1e30f;
                    }
                    sacc[nf][2*l + c] = s;
                    rm = fmaxf(rm, s);
                }
            }
            rm = fmaxf(rm, __shfl_xor_sync(0xffffffffu, rm, 1));
            rm = fmaxf(rm, __shfl_xor_sync(0xffffffffu, rm, 2));
            float mnew = fmaxf(m_[l], rm);
            float fac  = __expf(m_[l] - mnew);
            float ps = 0.0f;
            #pragma unroll
            for (int nf = 0; nf < 8; ++nf) {
                #pragma unroll
                for (int c = 0; c < 2; ++c) {
                    float p = __expf(sacc[nf][2*l + c] - mnew);
                    Ps[(nf*8 + 2*tig + c)*FSW + rloc] = f2tf(p);
                    ps += p;
                }
            }
            ps += __shfl_xor_sync(0xffffffffu, ps, 1);
            ps += __shfl_xor_sync(0xffffffffu, ps, 2);
            l_[l] = l_[l]*fac + ps;
            m_[l] = mnew;
            #pragma unroll
            for (int nf = 0; nf < 8; ++nf) {
                octx[nf][2*l + 0] *= fac;
                octx[nf][2*l + 1] *= fac;
            }
        }
        __syncwarp();

        #pragma unroll
        for (int ks = 0; ks < 8; ++ks) {
            const int kk = ks * 8;
            U32 af[4];
            af[0] = Ps[(kk + tig    )*FSW + wr + grp    ];
            af[1] = Ps[(kk + tig    )*FSW + wr + grp + 8];
            af[2] = Ps[(kk + tig + 4)*FSW + wr + grp    ];
            af[3] = Ps[(kk + tig + 4)*FSW + wr + grp + 8];
            #pragma unroll
            for (int nf = 0; nf < 8; ++nf) {
                U32 bf[2];
                bf[0] = Vs[(kk + tig    )*FSW + nf*8 + grp];
                bf[1] = Vs[(kk + tig + 4)*FSW + nf*8 + grp];
                mma8(octx[nf], af, bf);
            }
        }
    }

    float* op = g_ctx + (size_t)bh * NS * 64;
    #pragma unroll
    for (int l = 0; l < 2; ++l) {
        const int r  = q0 + wr + grp + 8*l;
        const float inv = 1.0f / l_[l];
        #pragma unroll
        for (int nf = 0; nf < 8; ++nf) {
            float2 f;
            f.x = octx[nf][2*l + 0] * inv;
            f.y = octx[nf][2*l + 1] * inv;
            *(float2*)(op + (size_t)r*64 + nf*8 + 2*tig) = f;
        }
    }
}

// ---------------------------------------------------------------------------
extern "C" void kernel_launch(void* const* d_in, const int* in_sizes, int n_in,
                              void* d_out, int out_size)
{
    const float* q  = (const float*)d_in[0];
    const float* k  = (const float*)d_in[1];
    const float* v  = (const float*)d_in[2];
    const float* Wq = (const float*)d_in[3];
    const float* Wk = (const float*)d_in[4];
    const float* Wv = (const float*)d_in[5];
    const float* Wo = (const float*)d_in[6];
    float* out = (float*)d_out;

    float *pq, *pk, *pv, *pctx;
    cudaGetSymbolAddress((void**)&pq,   g_q);
    cudaGetSymbolAddress((void**)&pk,   g_k);
    cudaGetSymbolAddress((void**)&pv,   g_v);
    cudaGetSymbolAddress((void**)&pctx, g_ctx);

    cudaFuncSetAttribute(flash_mma_kernel,
                         cudaFuncAttributeMaxDynamicSharedMemorySize,
                         FL_BYTES);

    rope_table_kernel<<<256, 256>>>();

    dim3 gg(NE/128, NM/128);               // (8, 32)
    gemm_mma<<<gg, 256>>>(q, Wq, pq, 0, 1, 1);   // Q proj + RoPE
    gemm_mma<<<gg, 256>>>(k, Wk, pk, 0, 1, 1);   // K proj + RoPE
    gemm_mma<<<gg, 256>>>(v, Wv, pv, 0, 1, 0);   // V proj

    dim3 fg(NS/64, NB*NH);                 // (32, 32)
    flash_mma_kernel<<<fg, 128, FL_BYTES>>>();

    gemm_mma<<<gg, 256>>>(pctx, Wo, out, 1, 0, 0);  // output proj
}

// round 8
// speedup vs baseline: 1.2838x; 1.1134x over previous
#include <cuda_runtime.h>
#include <math.h>

typedef unsigned long long ULL;
typedef unsigned int U32;

#define NB 2
#define NS 2048
#define NE 1024
#define NH 16
#define NHD 64
#define NM 4096                  // NB*NS
#define ATT_SCALE (1.0f/32.0f)   // 1/sqrt(1024), exact power of two

// ---------------- scratch (device globals; no allocation allowed) ----------
__device__ float g_q[NB*NH*NS*NHD];    // head-major: [b*16+h][s][hd]
__device__ float g_k[NB*NH*NS*NHD];
__device__ float g_v[NB*NH*NS*NHD];
__device__ float g_ctx[NB*NH*NS*NHD];
__device__ float g_cos[NS*32];
__device__ float g_sin[NS*32];

// ---------------- tf32 mma.sync helpers (works on plain sm_103) ------------
__device__ __forceinline__ U32 f2tf(float x){
    U32 u; asm("cvt.rn.tf32.f32 %0, %1;" : "=r"(u) : "f"(x)); return u;
}
__device__ __forceinline__ void mma8(float* c, const U32* a, const U32* b){
    asm volatile("mma.sync.aligned.m16n8k8.row.col.f32.tf32.tf32.f32 "
        "{%0,%1,%2,%3}, {%4,%5,%6,%7}, {%8,%9}, {%0,%1,%2,%3};"
        : "+f"(c[0]), "+f"(c[1]), "+f"(c[2]), "+f"(c[3])
        : "r"(a[0]), "r"(a[1]), "r"(a[2]), "r"(a[3]), "r"(b[0]), "r"(b[1]));
}

// ============================================================================
// Projection GEMM (R7, proven): 256 thr = 8 warps (2x4), warp tile 64x32,
// BK=16, permuted+swizzled smem, 2-stage double buffer, 1 sync/ktile.
// ============================================================================
#define GST 16384                // bytes per stage: A 8K + B 8K

__global__ void __launch_bounds__(256, 2)
gemm_mma(const float* __restrict__ A, const float* __restrict__ Wt,
         float* __restrict__ C, int a_heads, int c_heads, int do_rope)
{
    __shared__ __align__(16) char smem[2*GST];
    const int t    = threadIdx.x;
    const int lane = t & 31;
    const int wid  = t >> 5;
    const int grp  = lane >> 2;
    const int tig  = lane & 3;
    const int wm   = (wid & 1) * 64;
    const int wn   = (wid >> 1) * 32;
    const int bm   = blockIdx.y * 128;
    const int bn   = blockIdx.x * 128;

    const int ar   = t >> 1;
    const int ksP  = t & 1;
    const int mfA  = ar >> 4, gA = ar & 7, hiA = (ar >> 3) & 1;
    const int swSA = (gA >> 1) & 3;
    const int nfB  = ar >> 3, gB = ar & 7;
    const int swSB = ((gB >> 2) & 1) | ((nfB & 1) << 1);
    char* const pAa = smem + ksP*4096 + mfA*512 + gA*64 + hiA*4;
    char* const pBb = smem + 8192 + ksP*4096 + nfB*256 + gB*32;

    const int tigA = tig ^ ((grp >> 1) & 3);
    const int sbgl = (grp >> 2) & 1;

    float acc[4][4][4];
    #pragma unroll
    for (int i=0;i<4;++i)
        #pragma unroll
        for (int j=0;j<4;++j)
            #pragma unroll
            for (int r=0;r<4;++r) acc[i][j][r] = 0.0f;

    float4 av[2], bv[2];

    auto LDG = [&](int kt){
        const int e0 = kt*16 + ksP*8;
        const float* pa;
        if (!a_heads) pa = A + (size_t)(bm + ar)*NE + e0;
        else {
            int m = bm + ar, b = m >> 11, s = m & 2047;
            pa = A + ((size_t)((b*16 + (e0 >> 6))*NS + s))*64 + (e0 & 63);
        }
        const float* pb = Wt + (size_t)(bn + ar)*NE + e0;
        av[0] = *(const float4*)(pa);   av[1] = *(const float4*)(pa+4);
        bv[0] = *(const float4*)(pb);   bv[1] = *(const float4*)(pb+4);
    };

    auto STS = [&](int st){
        char* sA = pAa + st*GST;
        char* sB = pBb + st*GST;
        const float* afl = (const float*)av;
        const float* bfl = (const float*)bv;
        #pragma unroll
        for (int k = 0; k < 8; ++k) {
            int tg = k & 3, khi = (k >> 2) & 1;
            *(U32*)(sA + ((tg ^ swSA) << 4) + khi*8) = f2tf(afl[k]);
            *(U32*)(sB + ((tg ^ swSB) << 3) + khi*4) = f2tf(bfl[k]);
        }
    };

    auto MMA = [&](int st){
        char* sA = smem + st*GST;
        char* sB = sA + 8192;
        #pragma unroll
        for (int ks = 0; ks < 2; ++ks) {
            uint4 af[4];
            #pragma unroll
            for (int mf = 0; mf < 4; ++mf) {
                int mfi = (wm >> 4) + mf;
                af[mf] = *(const uint4*)(sA + ks*4096 + mfi*512 + grp*64 + (tigA << 4));
            }
            uint2 bf[4];
            #pragma unroll
            for (int nf = 0; nf < 4; ++nf) {
                int nfi = (wn >> 3) + nf;
                int tb  = tig ^ (sbgl | ((nfi & 1) << 1));
                bf[nf]  = *(const uint2*)(sB + ks*4096 + nfi*256 + grp*32 + (tb << 3));
            }
            #pragma unroll
            for (int mf = 0; mf < 4; ++mf)
                #pragma unroll
                for (int nf = 0; nf < 4; ++nf)
                    mma8(acc[mf][nf], (const U32*)&af[mf], (const U32*)&bf[nf]);
        }
    };

    LDG(0); STS(0); __syncthreads();
    for (int kt = 0; kt < 64; ++kt) {
        if (kt < 63) LDG(kt + 1);
        MMA(kt & 1);
        if (kt < 63) STS((kt + 1) & 1);
        __syncthreads();
    }

    #pragma unroll
    for (int mf = 0; mf < 4; ++mf) {
        #pragma unroll
        for (int half = 0; half < 2; ++half) {
            int m = bm + wm + mf*16 + grp + half*8;
            #pragma unroll
            for (int nf = 0; nf < 4; ++nf) {
                int n = bn + wn + nf*8 + 2*tig;
                float fx = acc[mf][nf][half*2 + 0];
                float fy = acc[mf][nf][half*2 + 1];
                if (do_rope) {
                    int s = m & 2047;
                    int p = (n & 63) >> 1;
                    float co = g_cos[s*32 + p], sn = g_sin[s*32 + p];
                    float rx = fx*co - fy*sn;
                    float ry = fx*sn + fy*co;
                    fx = rx; fy = ry;
                }
                float2 f = make_float2(fx, fy);
                if (!c_heads) {
                    *(float2*)(C + (size_t)m*NE + n) = f;
                } else {
                    int b = m >> 11, s2 = m & 2047;
                    *(float2*)(C + ((size_t)((b*16 + (n>>6))*NS + s2))*64 + (n & 63)) = f;
                }
            }
        }
    }
}

// ---------------- RoPE table -----------------------------------------------
__global__ void rope_table_kernel()
{
    int idx = blockIdx.x * blockDim.x + threadIdx.x;   // 65536
    if (idx >= NS*32) return;
    int s = idx >> 5, p = idx & 31;
    double invf = 1.0 / pow(10000.0, (double)(2*p) / 64.0);
    double a = (double)s * invf;
    g_cos[idx] = (float)cos(a);
    g_sin[idx] = (float)sin(a);
}

// ============================================================================
// Flash attention v2: packed-fragment smem layouts (mirrors gemm scheme).
// Tile 64x64, 128 thr = 4 warps (16 q-rows each).
//   A-layout (Q stage / P^T), 64x64: 16B group at
//     ks*2048 + mf*512 + grp*64 + ((tg^((grp>>1)&3))<<4) + khi*8 + hi*4
//     = { X[mf*16+grp+8*hi][ks*8+tg+4*khi] }  in mma a0..a3 order.
//   B-layout (K / V^T), 64(n)x64(k): 8B group at
//     ks*2048 + nf*256 + grp*32 + ((tg ^ (((grp>>2)&1)|((nf&1)<<1)) ^ (ks&3))<<3)
//     = { Y[n=nf*8+grp][k=ks*8+tg], Y[n][k+4] }.
// Q frags live in registers (loaded once). smem = 48KB static.
// ============================================================================
__global__ void __launch_bounds__(128)
flash_mma_kernel()
{
    __shared__ __align__(16) char fsm[49152];
    char* Ks = fsm;                 // B-layout, n=kv col, k=hd
    char* Vs = fsm + 16384;         // B-layout, n=hd,    k=kv col
    char* Ps = fsm + 32768;         // A-layout P^T; doubles as Q staging

    const int t    = threadIdx.x;
    const int lane = t & 31;
    const int wid  = t >> 5;
    const int grp  = lane >> 2;          // 0..7
    const int tig  = lane & 3;           // 0..3
    const int wr   = wid * 16;
    const int mfW  = wid;                // wr>>4
    const int tigA = tig ^ ((grp >> 1) & 3);
    const int bh   = blockIdx.y;
    const int qb   = (int)gridDim.x - 1 - (int)blockIdx.x;  // heavy first
    const int q0   = qb * 64;

    const float* qp = g_q + (size_t)bh * NS * 64;
    const float* kp = g_k + (size_t)bh * NS * 64;
    const float* vp = g_v + (size_t)bh * NS * 64;

    // ---- stage Q (scaled) into Ps using A-layout ----
    {
        const int r = t >> 1, ksP = t & 1;
        const int mf = r >> 4, g = r & 7, hi = (r >> 3) & 1;
        const int swz = (g >> 1) & 3;
        const float* pq = qp + (size_t)(q0 + r)*64 + ksP*32;
        char* base = Ps + mf*512 + g*64 + hi*4;
        #pragma unroll
        for (int j8 = 0; j8 < 4; ++j8) {
            float4 f0 = *(const float4*)(pq + j8*8);
            float4 f1 = *(const float4*)(pq + j8*8 + 4);
            int ks = ksP*4 + j8;
            float vals[8] = {f0.x,f0.y,f0.z,f0.w,f1.x,f1.y,f1.z,f1.w};
            #pragma unroll
            for (int j = 0; j < 8; ++j) {
                int tg = j & 3, khi = j >> 2;
                *(U32*)(base + ks*2048 + ((tg^swz)<<4) + khi*8) =
                    f2tf(vals[j] * ATT_SCALE);
            }
        }
    }
    __syncthreads();

    // ---- Q fragments -> registers (8 ks x 4 words) ----
    U32 qf[8][4];
    #pragma unroll
    for (int ks = 0; ks < 8; ++ks)
        *(uint4*)qf[ks] =
            *(const uint4*)(Ps + ks*2048 + mfW*512 + grp*64 + (tigA<<4));
    // (Ps is overwritten by P only after the loop's first __syncthreads)

    float m_[2], l_[2];
    m_[0] = m_[1] = -1e30f;
    l_[0] = l_[1] = 0.0f;
    float octx[8][4];
    #pragma unroll
    for (int nf=0;nf<8;++nf)
        #pragma unroll
        for (int r=0;r<4;++r) octx[nf][r] = 0.0f;

    for (int kb = 0; kb <= qb; ++kb) {
        const int k0 = kb * 64;
        if (kb) __syncthreads();          // prev PV done before K/V overwrite

        // ---- K producer: B-layout(n=col, k=hd) ----
        #pragma unroll
        for (int it = 0; it < 4; ++it) {
            int idx = it*128 + t;         // 0..511
            int c = idx >> 3, o = idx & 7;
            const float* pk = kp + (size_t)(k0 + c)*64 + o*8;
            float4 f0 = *(const float4*)pk;
            float4 f1 = *(const float4*)(pk+4);
            float vals[8] = {f0.x,f0.y,f0.z,f0.w,f1.x,f1.y,f1.z,f1.w};
            int nf = c >> 3, g = c & 7;
            int swb = ((g>>2)&1) | ((nf&1)<<1);
            char* base = Ks + o*2048 + nf*256 + g*32;
            #pragma unroll
            for (int tg = 0; tg < 4; ++tg) {
                uint2 u;
                u.x = f2tf(vals[tg]);
                u.y = f2tf(vals[tg+4]);
                *(uint2*)(base + ((tg ^ swb ^ (o&3))<<3)) = u;
            }
        }
        // ---- V producer: B-layout(n=hd, k=col) ----
        #pragma unroll
        for (int it = 0; it < 4; ++it) {
            int idx = it*128 + t;         // 0..511
            int rp = idx >> 4, qq = idx & 15;
            int ks = rp >> 2, tg = rp & 3;
            int c = ks*8 + tg;
            const float* pv0 = vp + (size_t)(k0 + c)*64 + qq*4;
            const float* pv1 = vp + (size_t)(k0 + c + 4)*64 + qq*4;
            float4 f0 = *(const float4*)pv0;
            float4 f1 = *(const float4*)pv1;
            float lo4[4] = {f0.x,f0.y,f0.z,f0.w};
            float hi4[4] = {f1.x,f1.y,f1.z,f1.w};
            #pragma unroll
            for (int dn = 0; dn < 4; ++dn) {
                int n = qq*4 + dn, nf = n>>3, g = n&7;
                int swb = ((g>>2)&1) | ((nf&1)<<1);
                uint2 u;
                u.x = f2tf(lo4[dn]);
                u.y = f2tf(hi4[dn]);
                *(uint2*)(Vs + ks*2048 + nf*256 + g*32
                             + ((tg ^ swb ^ (ks&3))<<3)) = u;
            }
        }
        __syncthreads();

        // ---- S = Q @ K^T ----
        float sacc[8][4];
        #pragma unroll
        for (int nf=0;nf<8;++nf)
            #pragma unroll
            for (int r=0;r<4;++r) sacc[nf][r] = 0.0f;
        #pragma unroll
        for (int ks = 0; ks < 8; ++ks) {
            #pragma unroll
            for (int nf = 0; nf < 8; ++nf) {
                int tb = tig ^ (((grp>>2)&1) | ((nf&1)<<1)) ^ (ks&3);
                uint2 bf = *(const uint2*)(Ks + ks*2048 + nf*256
                                              + grp*32 + (tb<<3));
                mma8(sacc[nf], qf[ks], (const U32*)&bf);
            }
        }

        // ---- online softmax; write P^T in A-layout ----
        const bool diag = (kb == qb);
        #pragma unroll
        for (int l = 0; l < 2; ++l) {
            const int rloc = wr + grp + 8*l;
            const int gi   = q0 + rloc;
            float rm = -1e30f;
            #pragma unroll
            for (int nf = 0; nf < 8; ++nf) {
                #pragma unroll
                for (int c = 0; c < 2; ++c) {
                    float s = sacc[nf][2*l + c];
                    if (diag) {
                        int gj = k0 + nf*8 + 2*tig + c;
                        if (gj >= gi && !(gi == 0 && gj == 0)) s = -1e30f;
                    }
                    sacc[nf][2*l + c] = s;
                    rm = fmaxf(rm, s);
                }
            }
            rm = fmaxf(rm, __shfl_xor_sync(0xffffffffu, rm, 1));
            rm = fmaxf(rm, __shfl_xor_sync(0xffffffffu, rm, 2));
            float mnew = fmaxf(m_[l], rm);
            float fac  = __expf(m_[l] - mnew);
            float ps = 0.0f;
            char* pbase = Ps + mfW*512 + grp*64 + l*4;
            const int swzP = (grp >> 1) & 3;
            #pragma unroll
            for (int nf = 0; nf < 8; ++nf) {
                #pragma unroll
                for (int c = 0; c < 2; ++c) {
                    float p = __expf(sacc[nf][2*l + c] - mnew);
                    int j = 2*tig + c;            // k within octet
                    int tg = j & 3, khi = j >> 2;
                    *(U32*)(pbase + nf*2048 + ((tg^swzP)<<4) + khi*8) = f2tf(p);
                    ps += p;
                }
            }
            ps += __shfl_xor_sync(0xffffffffu, ps, 1);
            ps += __shfl_xor_sync(0xffffffffu, ps, 2);
            l_[l] = l_[l]*fac + ps;
            m_[l] = mnew;
            #pragma unroll
            for (int nf = 0; nf < 8; ++nf) {
                octx[nf][2*l + 0] *= fac;
                octx[nf][2*l + 1] *= fac;
            }
        }
        __syncwarp();                     // P^T region is warp-private

        // ---- ctx += P @ V ----
        #pragma unroll
        for (int ks = 0; ks < 8; ++ks) {
            uint4 af = *(const uint4*)(Ps + ks*2048 + mfW*512
                                          + grp*64 + (tigA<<4));
            #pragma unroll
            for (int nf = 0; nf < 8; ++nf) {
                int tb = tig ^ (((grp>>2)&1) | ((nf&1)<<1)) ^ (ks&3);
                uint2 bf = *(const uint2*)(Vs + ks*2048 + nf*256
                                              + grp*32 + (tb<<3));
                mma8(octx[nf], (const U32*)&af, (const U32*)&bf);
            }
        }
    }

    // ---- normalize + write ctx (head-major) ----
    float* op = g_ctx + (size_t)bh * NS * 64;
    #pragma unroll
    for (int l = 0; l < 2; ++l) {
        const int r  = q0 + wr + grp + 8*l;
        const float inv = 1.0f / l_[l];
        #pragma unroll
        for (int nf = 0; nf < 8; ++nf) {
            float2 f;
            f.x = octx[nf][2*l + 0] * inv;
            f.y = octx[nf][2*l + 1] * inv;
            *(float2*)(op + (size_t)r*64 + nf*8 + 2*tig) = f;
        }
    }
}

// ---------------------------------------------------------------------------
extern "C" void kernel_launch(void* const* d_in, const int* in_sizes, int n_in,
                              void* d_out, int out_size)
{
    const float* q  = (const float*)d_in[0];
    const float* k  = (const float*)d_in[1];
    const float* v  = (const float*)d_in[2];
    const float* Wq = (const float*)d_in[3];
    const float* Wk = (const float*)d_in[4];
    const float* Wv = (const float*)d_in[5];
    const float* Wo = (const float*)d_in[6];
    float* out = (float*)d_out;

    float *pq, *pk, *pv, *pctx;
    cudaGetSymbolAddress((void**)&pq,   g_q);
    cudaGetSymbolAddress((void**)&pk,   g_k);
    cudaGetSymbolAddress((void**)&pv,   g_v);
    cudaGetSymbolAddress((void**)&pctx, g_ctx);

    rope_table_kernel<<<256, 256>>>();

    dim3 gg(NE/128, NM/128);               // (8, 32)
    gemm_mma<<<gg, 256>>>(q, Wq, pq, 0, 1, 1);   // Q proj + RoPE
    gemm_mma<<<gg, 256>>>(k, Wk, pk, 0, 1, 1);   // K proj + RoPE
    gemm_mma<<<gg, 256>>>(v, Wv, pv, 0, 1, 0);   // V proj

    dim3 fg(NS/64, NB*NH);                 // (32, 32)
    flash_mma_kernel<<<fg, 128>>>();

    gemm_mma<<<gg, 256>>>(pctx, Wo, out, 1, 0, 0);  // output proj
}

// round 9
// speedup vs baseline: 1.3061x; 1.0174x over previous
#include <cuda_runtime.h>
#include <math.h>

typedef unsigned long long ULL;
typedef unsigned int U32;

#define NB 2
#define NS 2048
#define NE 1024
#define NH 16
#define NHD 64
#define NM 4096                  // NB*NS
#define ATT_SCALE (1.0f/32.0f)   // 1/sqrt(1024), exact power of two

// ---------------- scratch (device globals; no allocation allowed) ----------
__device__ float g_q[NB*NH*NS*NHD];    // head-major: [b*16+h][s][hd]
__device__ float g_k[NB*NH*NS*NHD];
__device__ float g_v[NB*NH*NS*NHD];
__device__ float g_ctx[NB*NH*NS*NHD];
__device__ float g_cos[NS*32];
__device__ float g_sin[NS*32];

// ---------------- tf32 mma.sync helpers (works on plain sm_103) ------------
__device__ __forceinline__ U32 f2tf(float x){
    U32 u; asm("cvt.rn.tf32.f32 %0, %1;" : "=r"(u) : "f"(x)); return u;
}
__device__ __forceinline__ void mma8(float* c, const U32* a, const U32* b){
    asm volatile("mma.sync.aligned.m16n8k8.row.col.f32.tf32.tf32.f32 "
        "{%0,%1,%2,%3}, {%4,%5,%6,%7}, {%8,%9}, {%0,%1,%2,%3};"
        : "+f"(c[0]), "+f"(c[1]), "+f"(c[2]), "+f"(c[3])
        : "r"(a[0]), "r"(a[1]), "r"(a[2]), "r"(a[3]), "r"(b[0]), "r"(b[1]));
}
// permuted variant: memory word order (a0,a2,a1,a3) -> operands (x,z,y,w)
__device__ __forceinline__ void mma8p(float* c, uint4 a, uint2 b){
    asm volatile("mma.sync.aligned.m16n8k8.row.col.f32.tf32.tf32.f32 "
        "{%0,%1,%2,%3}, {%4,%5,%6,%7}, {%8,%9}, {%0,%1,%2,%3};"
        : "+f"(c[0]), "+f"(c[1]), "+f"(c[2]), "+f"(c[3])
        : "r"(a.x), "r"(a.z), "r"(a.y), "r"(a.w), "r"(b.x), "r"(b.y));
}

// ============================================================================
// Projection GEMM v4: 256 thr = 8 warps (2x4), warp tile 64x32, BK=16,
// 2-stage double buffer, 1 sync/ktile. Wide producer stores (STS.64).
//
// A-group(ks,mf,grp,tg) 16B, word order [hi][khi]:
//   byte = ks*4096 + mf*512 + grp*64 + ((tg^((grp>>1)&3))<<4) + hi*8 + khi*4
//   holds A[mf*16+grp+8*hi][ks*8+tg+4*khi]  (mma order a0,a2,a1,a3 -> mma8p)
// B-group(ks,nf,grp,tg) 8B:
//   byte = ks*4096 + nf*256 + grp*32 + ((tg^(((grp>>2)&1)|((nf&1)<<1)))<<3) + khi*4
//   holds B[nf*8+grp][ks*8+tg+4*khi]
// ============================================================================
#define GST 16384                // bytes per stage: A 8K + B 8K

__global__ void __launch_bounds__(256, 2)
gemm_mma(const float* __restrict__ A, const float* __restrict__ Wt,
         float* __restrict__ C, int a_heads, int c_heads, int do_rope)
{
    __shared__ __align__(16) char smem[2*GST];
    const int t    = threadIdx.x;
    const int lane = t & 31;
    const int wid  = t >> 5;
    const int grp  = lane >> 2;
    const int tig  = lane & 3;
    const int wm   = (wid & 1) * 64;
    const int wn   = (wid >> 1) * 32;
    const int bm   = blockIdx.y * 128;
    const int bn   = blockIdx.x * 128;

    // producer constants: thread owns A-row ar / B-row ar, k-octet ksP
    const int ar   = t >> 1;             // 0..127
    const int ksP  = t & 1;
    const int mfA  = ar >> 4, gA = ar & 7, hiA = (ar >> 3) & 1;
    const int swSA = (gA >> 1) & 3;
    const int nfB  = ar >> 3, gB = ar & 7;
    const int swSB = ((gB >> 2) & 1) | ((nfB & 1) << 1);
    char* const pAa = smem + ksP*4096 + mfA*512 + gA*64 + hiA*8;
    char* const pBb = smem + 8192 + ksP*4096 + nfB*256 + gB*32;

    // consumer constants
    const int tigA = tig ^ ((grp >> 1) & 3);
    const int sbgl = (grp >> 2) & 1;

    float acc[4][4][4];
    #pragma unroll
    for (int i=0;i<4;++i)
        #pragma unroll
        for (int j=0;j<4;++j)
            #pragma unroll
            for (int r=0;r<4;++r) acc[i][j][r] = 0.0f;

    float4 av[2], bv[2];

    auto LDG = [&](int kt){
        const int e0 = kt*16 + ksP*8;
        const float* pa;
        if (!a_heads) pa = A + (size_t)(bm + ar)*NE + e0;
        else {
            int m = bm + ar, b = m >> 11, s = m & 2047;
            pa = A + ((size_t)((b*16 + (e0 >> 6))*NS + s))*64 + (e0 & 63);
        }
        const float* pb = Wt + (size_t)(bn + ar)*NE + e0;
        av[0] = *(const float4*)(pa);   av[1] = *(const float4*)(pa+4);
        bv[0] = *(const float4*)(pb);   bv[1] = *(const float4*)(pb+4);
    };

    auto STS = [&](int st){
        char* sA = pAa + st*GST;
        char* sB = pBb + st*GST;
        const float* afl = (const float*)av;
        const float* bfl = (const float*)bv;
        #pragma unroll
        for (int tg = 0; tg < 4; ++tg) {
            uint2 ua, ub;
            ua.x = f2tf(afl[tg]);  ua.y = f2tf(afl[tg+4]);
            ub.x = f2tf(bfl[tg]);  ub.y = f2tf(bfl[tg+4]);
            *(uint2*)(sA + ((tg ^ swSA) << 4)) = ua;
            *(uint2*)(sB + ((tg ^ swSB) << 3)) = ub;
        }
    };

    auto MMA = [&](int st){
        char* sA = smem + st*GST;
        char* sB = sA + 8192;
        #pragma unroll
        for (int ks = 0; ks < 2; ++ks) {
            uint4 af[4];
            #pragma unroll
            for (int mf = 0; mf < 4; ++mf) {
                int mfi = (wm >> 4) + mf;
                af[mf] = *(const uint4*)(sA + ks*4096 + mfi*512 + grp*64 + (tigA << 4));
            }
            uint2 bf[4];
            #pragma unroll
            for (int nf = 0; nf < 4; ++nf) {
                int nfi = (wn >> 3) + nf;
                int tb  = tig ^ (sbgl | ((nfi & 1) << 1));
                bf[nf]  = *(const uint2*)(sB + ks*4096 + nfi*256 + grp*32 + (tb << 3));
            }
            #pragma unroll
            for (int mf = 0; mf < 4; ++mf)
                #pragma unroll
                for (int nf = 0; nf < 4; ++nf)
                    mma8p(acc[mf][nf], af[mf], bf[nf]);
        }
    };

    LDG(0); STS(0); __syncthreads();
    for (int kt = 0; kt < 64; ++kt) {
        if (kt < 63) LDG(kt + 1);
        MMA(kt & 1);
        if (kt < 63) STS((kt + 1) & 1);
        __syncthreads();
    }

    // epilogue (+ optional fused RoPE: float2 = one (even,odd) hd pair)
    #pragma unroll
    for (int mf = 0; mf < 4; ++mf) {
        #pragma unroll
        for (int half = 0; half < 2; ++half) {
            int m = bm + wm + mf*16 + grp + half*8;
            #pragma unroll
            for (int nf = 0; nf < 4; ++nf) {
                int n = bn + wn + nf*8 + 2*tig;
                float fx = acc[mf][nf][half*2 + 0];
                float fy = acc[mf][nf][half*2 + 1];
                if (do_rope) {
                    int s = m & 2047;
                    int p = (n & 63) >> 1;
                    float co = g_cos[s*32 + p], sn = g_sin[s*32 + p];
                    float rx = fx*co - fy*sn;
                    float ry = fx*sn + fy*co;
                    fx = rx; fy = ry;
                }
                float2 f = make_float2(fx, fy);
                if (!c_heads) {
                    *(float2*)(C + (size_t)m*NE + n) = f;
                } else {
                    int b = m >> 11, s2 = m & 2047;
                    *(float2*)(C + ((size_t)((b*16 + (n>>6))*NS + s2))*64 + (n & 63)) = f;
                }
            }
        }
    }
}

// ---------------- RoPE table -----------------------------------------------
__global__ void rope_table_kernel()
{
    int idx = blockIdx.x * blockDim.x + threadIdx.x;   // 65536
    if (idx >= NS*32) return;
    int s = idx >> 5, p = idx & 31;
    double invf = 1.0 / pow(10000.0, (double)(2*p) / 64.0);
    double a = (double)s * invf;
    g_cos[idx] = (float)cos(a);
    g_sin[idx] = (float)sin(a);
}

// ============================================================================
// Flash attention v2 (R8, proven): packed-fragment smem layouts.
// Tile 64x64, 128 thr = 4 warps (16 q-rows each).  UNCHANGED.
// ============================================================================
__global__ void __launch_bounds__(128)
flash_mma_kernel()
{
    __shared__ __align__(16) char fsm[49152];
    char* Ks = fsm;                 // B-layout, n=kv col, k=hd
    char* Vs = fsm + 16384;         // B-layout, n=hd,    k=kv col
    char* Ps = fsm + 32768;         // A-layout P^T; doubles as Q staging

    const int t    = threadIdx.x;
    const int lane = t & 31;
    const int wid  = t >> 5;
    const int grp  = lane >> 2;          // 0..7
    const int tig  = lane & 3;           // 0..3
    const int wr   = wid * 16;
    const int mfW  = wid;
    const int tigA = tig ^ ((grp >> 1) & 3);
    const int bh   = blockIdx.y;
    const int qb   = (int)gridDim.x - 1 - (int)blockIdx.x;  // heavy first
    const int q0   = qb * 64;

    const float* qp = g_q + (size_t)bh * NS * 64;
    const float* kp = g_k + (size_t)bh * NS * 64;
    const float* vp = g_v + (size_t)bh * NS * 64;

    // ---- stage Q (scaled) into Ps using A-layout ----
    {
        const int r = t >> 1, ksP = t & 1;
        const int mf = r >> 4, g = r & 7, hi = (r >> 3) & 1;
        const int swz = (g >> 1) & 3;
        const float* pq = qp + (size_t)(q0 + r)*64 + ksP*32;
        char* base = Ps + mf*512 + g*64 + hi*4;
        #pragma unroll
        for (int j8 = 0; j8 < 4; ++j8) {
            float4 f0 = *(const float4*)(pq + j8*8);
            float4 f1 = *(const float4*)(pq + j8*8 + 4);
            int ks = ksP*4 + j8;
            float vals[8] = {f0.x,f0.y,f0.z,f0.w,f1.x,f1.y,f1.z,f1.w};
            #pragma unroll
            for (int j = 0; j < 8; ++j) {
                int tg = j & 3, khi = j >> 2;
                *(U32*)(base + ks*2048 + ((tg^swz)<<4) + khi*8) =
                    f2tf(vals[j] * ATT_SCALE);
            }
        }
    }
    __syncthreads();

    // ---- Q fragments -> registers (8 ks x 4 words) ----
    U32 qf[8][4];
    #pragma unroll
    for (int ks = 0; ks < 8; ++ks)
        *(uint4*)qf[ks] =
            *(const uint4*)(Ps + ks*2048 + mfW*512 + grp*64 + (tigA<<4));

    float m_[2], l_[2];
    m_[0] = m_[1] = -1e30f;
    l_[0] = l_[1] = 0.0f;
    float octx[8][4];
    #pragma unroll
    for (int nf=0;nf<8;++nf)
        #pragma unroll
        for (int r=0;r<4;++r) octx[nf][r] = 0.0f;

    for (int kb = 0; kb <= qb; ++kb) {
        const int k0 = kb * 64;
        if (kb) __syncthreads();

        // ---- K producer: B-layout(n=col, k=hd) ----
        #pragma unroll
        for (int it = 0; it < 4; ++it) {
            int idx = it*128 + t;
            int c = idx >> 3, o = idx & 7;
            const float* pk = kp + (size_t)(k0 + c)*64 + o*8;
            float4 f0 = *(const float4*)pk;
            float4 f1 = *(const float4*)(pk+4);
            float vals[8] = {f0.x,f0.y,f0.z,f0.w,f1.x,f1.y,f1.z,f1.w};
            int nf = c >> 3, g = c & 7;
            int swb = ((g>>2)&1) | ((nf&1)<<1);
            char* base = Ks + o*2048 + nf*256 + g*32;
            #pragma unroll
            for (int tg = 0; tg < 4; ++tg) {
                uint2 u;
                u.x = f2tf(vals[tg]);
                u.y = f2tf(vals[tg+4]);
                *(uint2*)(base + ((tg ^ swb ^ (o&3))<<3)) = u;
            }
        }
        // ---- V producer: B-layout(n=hd, k=col) ----
        #pragma unroll
        for (int it = 0; it < 4; ++it) {
            int idx = it*128 + t;
            int rp = idx >> 4, qq = idx & 15;
            int ks = rp >> 2, tg = rp & 3;
            int c = ks*8 + tg;
            const float* pv0 = vp + (size_t)(k0 + c)*64 + qq*4;
            const float* pv1 = vp + (size_t)(k0 + c + 4)*64 + qq*4;
            float4 f0 = *(const float4*)pv0;
            float4 f1 = *(const float4*)pv1;
            float lo4[4] = {f0.x,f0.y,f0.z,f0.w};
            float hi4[4] = {f1.x,f1.y,f1.z,f1.w};
            #pragma unroll
            for (int dn = 0; dn < 4; ++dn) {
                int n = qq*4 + dn, nf = n>>3, g = n&7;
                int swb = ((g>>2)&1) | ((nf&1)<<1);
                uint2 u;
                u.x = f2tf(lo4[dn]);
                u.y = f2tf(hi4[dn]);
                *(uint2*)(Vs + ks*2048 + nf*256 + g*32
                             + ((tg ^ swb ^ (ks&3))<<3)) = u;
            }
        }
        __syncthreads();

        // ---- S = Q @ K^T ----
        float sacc[8][4];
        #pragma unroll
        for (int nf=0;nf<8;++nf)
            #pragma unroll
            for (int r=0;r<4;++r) sacc[nf][r] = 0.0f;
        #pragma unroll
        for (int ks = 0; ks < 8; ++ks) {
            #pragma unroll
            for (int nf = 0; nf < 8; ++nf) {
                int tb = tig ^ (((grp>>2)&1) | ((nf&1)<<1)) ^ (ks&3);
                uint2 bf = *(const uint2*)(Ks + ks*2048 + nf*256
                                              + grp*32 + (tb<<3));
                mma8(sacc[nf], qf[ks], (const U32*)&bf);
            }
        }

        // ---- online softmax; write P^T in A-layout ----
        const bool diag = (kb == qb);
        #pragma unroll
        for (int l = 0; l < 2; ++l) {
            const int rloc = wr + grp + 8*l;
            const int gi   = q0 + rloc;
            float rm = -1e30f;
            #pragma unroll
            for (int nf = 0; nf < 8; ++nf) {
                #pragma unroll
                for (int c = 0; c < 2; ++c) {
                    float s = sacc[nf][2*l + c];
                    if (diag) {
                        int gj = k0 + nf*8 + 2*tig + c;
                        if (gj >= gi && !(gi == 0 && gj == 0)) s = -1e30f;
                    }
                    sacc[nf][2*l + c] = s;
                    rm = fmaxf(rm, s);
                }
            }
            rm = fmaxf(rm, __shfl_xor_sync(0xffffffffu, rm, 1));
            rm = fmaxf(rm, __shfl_xor_sync(0xffffffffu, rm, 2));
            float mnew = fmaxf(m_[l], rm);
            float fac  = __expf(m_[l] - mnew);
            float ps = 0.0f;
            char* pbase = Ps + mfW*512 + grp*64 + l*4;
            const int swzP = (grp >> 1) & 3;
            #pragma unroll
            for (int nf = 0; nf < 8; ++nf) {
                #pragma unroll
                for (int c = 0; c < 2; ++c) {
                    float p = __expf(sacc[nf][2*l + c] - mnew);
                    int j = 2*tig + c;
                    int tg = j & 3, khi = j >> 2;
                    *(U32*)(pbase + nf*2048 + ((tg^swzP)<<4) + khi*8) = f2tf(p);
                    ps += p;
                }
            }
            ps += __shfl_xor_sync(0xffffffffu, ps, 1);
            ps += __shfl_xor_sync(0xffffffffu, ps, 2);
            l_[l] = l_[l]*fac + ps;
            m_[l] = mnew;
            #pragma unroll
            for (int nf = 0; nf < 8; ++nf) {
                octx[nf][2*l + 0] *= fac;
                octx[nf][2*l + 1] *= fac;
            }
        }
        __syncwarp();

        // ---- ctx += P @ V ----
        #pragma unroll
        for (int ks = 0; ks < 8; ++ks) {
            uint4 af = *(const uint4*)(Ps + ks*2048 + mfW*512
                                          + grp*64 + (tigA<<4));
            #pragma unroll
            for (int nf = 0; nf < 8; ++nf) {
                int tb = tig ^ (((grp>>2)&1) | ((nf&1)<<1)) ^ (ks&3);
                uint2 bf = *(const uint2*)(Vs + ks*2048 + nf*256
                                              + grp*32 + (tb<<3));
                mma8(octx[nf], (const U32*)&af, (const U32*)&bf);
            }
        }
    }

    // ---- normalize + write ctx (head-major) ----
    float* op = g_ctx + (size_t)bh * NS * 64;
    #pragma unroll
    for (int l = 0; l < 2; ++l) {
        const int r  = q0 + wr + grp + 8*l;
        const float inv = 1.0f / l_[l];
        #pragma unroll
        for (int nf = 0; nf < 8; ++nf) {
            float2 f;
            f.x = octx[nf][2*l + 0] * inv;
            f.y = octx[nf][2*l + 1] * inv;
            *(float2*)(op + (size_t)r*64 + nf*8 + 2*tig) = f;
        }
    }
}

// ---------------------------------------------------------------------------
extern "C" void kernel_launch(void* const* d_in, const int* in_sizes, int n_in,
                              void* d_out, int out_size)
{
    const float* q  = (const float*)d_in[0];
    const float* k  = (const float*)d_in[1];
    const float* v  = (const float*)d_in[2];
    const float* Wq = (const float*)d_in[3];
    const float* Wk = (const float*)d_in[4];
    const float* Wv = (const float*)d_in[5];
    const float* Wo = (const float*)d_in[6];
    float* out = (float*)d_out;

    float *pq, *pk, *pv, *pctx;
    cudaGetSymbolAddress((void**)&pq,   g_q);
    cudaGetSymbolAddress((void**)&pk,   g_k);
    cudaGetSymbolAddress((void**)&pv,   g_v);
    cudaGetSymbolAddress((void**)&pctx, g_ctx);

    rope_table_kernel<<<256, 256>>>();

    dim3 gg(NE/128, NM/128);               // (8, 32)
    gemm_mma<<<gg, 256>>>(q, Wq, pq, 0, 1, 1);   // Q proj + RoPE
    gemm_mma<<<gg, 256>>>(k, Wk, pk, 0, 1, 1);   // K proj + RoPE
    gemm_mma<<<gg, 256>>>(v, Wv, pv, 0, 1, 0);   // V proj

    dim3 fg(NS/64, NB*NH);                 // (32, 32)
    flash_mma_kernel<<<fg, 128>>>();

    gemm_mma<<<gg, 256>>>(pctx, Wo, out, 1, 0, 0);  // output proj
}

// round 10
// speedup vs baseline: 1.4245x; 1.0906x over previous
#include <cuda_runtime.h>
#include <math.h>

typedef unsigned long long ULL;
typedef unsigned int U32;

#define NB 2
#define NS 2048
#define NE 1024
#define NH 16
#define NHD 64
#define NM 4096                  // NB*NS
#define ATT_SCALE (1.0f/32.0f)   // 1/sqrt(1024), exact power of two

// ---------------- scratch (device globals; no allocation allowed) ----------
__device__ float g_q[NB*NH*NS*NHD];    // head-major: [b*16+h][s][hd]
__device__ float g_k[NB*NH*NS*NHD];
__device__ float g_v[NB*NH*NS*NHD];
__device__ float g_ctx[NB*NH*NS*NHD];  // written tf32-rounded by flash
__device__ float g_cos[NS*32];
__device__ float g_sin[NS*32];
// pre-converted tf32-bit operands
__device__ U32 g_qc[NM*NE];
__device__ U32 g_kc[NM*NE];
__device__ U32 g_vc[NM*NE];
__device__ U32 g_wqc[NE*NE];
__device__ U32 g_wkc[NE*NE];
__device__ U32 g_wvc[NE*NE];
__device__ U32 g_woc[NE*NE];

// ---------------- helpers ---------------------------------------------------
__device__ __forceinline__ U32 f2tf(float x){
    U32 u; asm("cvt.rn.tf32.f32 %0, %1;" : "=r"(u) : "f"(x)); return u;
}
__device__ __forceinline__ void mma8(float* c, const U32* a, const U32* b){
    asm volatile("mma.sync.aligned.m16n8k8.row.col.f32.tf32.tf32.f32 "
        "{%0,%1,%2,%3}, {%4,%5,%6,%7}, {%8,%9}, {%0,%1,%2,%3};"
        : "+f"(c[0]), "+f"(c[1]), "+f"(c[2]), "+f"(c[3])
        : "r"(a[0]), "r"(a[1]), "r"(a[2]), "r"(a[3]), "r"(b[0]), "r"(b[1]));
}
__device__ __forceinline__ U32 smem_u32(const void* p){
    U32 a;
    asm("{ .reg .u64 t; cvta.to.shared.u64 t, %1; cvt.u32.u64 %0, t; }"
        : "=r"(a) : "l"(p));
    return a;
}
__device__ __forceinline__ void ldsm4(U32* r, U32 a){
    asm volatile("ldmatrix.sync.aligned.m8n8.x4.shared.b16 {%0,%1,%2,%3}, [%4];"
        : "=r"(r[0]), "=r"(r[1]), "=r"(r[2]), "=r"(r[3]) : "r"(a));
}
__device__ __forceinline__ void ldsm2(U32* r, U32 a){
    asm volatile("ldmatrix.sync.aligned.m8n8.x2.shared.b16 {%0,%1}, [%2];"
        : "=r"(r[0]), "=r"(r[1]) : "r"(a));
}
__device__ __forceinline__ void cpa16(U32 dst, const void* src){
    asm volatile("cp.async.cg.shared.global [%0], [%1], 16;"
                 :: "r"(dst), "l"(src) : "memory");
}

// ---------------- prep: fp32 -> tf32 bits (RN) ------------------------------
#define Q4 (NM*NE/4)             // 1048576 float4 per input
#define W4 (NE*NE/4)             // 262144 float4 per weight
__global__ void prep_kernel(const float4* __restrict__ q, const float4* __restrict__ k,
                            const float4* __restrict__ v, const float4* __restrict__ wq,
                            const float4* __restrict__ wk, const float4* __restrict__ wv,
                            const float4* __restrict__ wo)
{
    int i = blockIdx.x * blockDim.x + threadIdx.x;   // 0 .. 3*Q4+4*W4-1
    const float4* s; uint4* d;
    if      (i <   Q4) { s = q + i;        d = (uint4*)g_qc + i; }
    else if (i < 2*Q4) { s = k + (i-Q4);   d = (uint4*)g_kc + (i-Q4); }
    else if (i < 3*Q4) { s = v + (i-2*Q4); d = (uint4*)g_vc + (i-2*Q4); }
    else {
        int j = i - 3*Q4, w = j / W4, o = j - w*W4;
        const float4* ws[4] = {wq, wk, wv, wo};
        uint4* wd[4] = {(uint4*)g_wqc, (uint4*)g_wkc, (uint4*)g_wvc, (uint4*)g_woc};
        s = ws[w] + o; d = wd[w] + o;
    }
    float4 f = *s;
    *d = make_uint4(f2tf(f.x), f2tf(f.y), f2tf(f.z), f2tf(f.w));
}

// ============================================================================
// Projection GEMM v5: cp.async 3-stage + ldmatrix. 256 thr = 8 warps (2x4),
// warp tile 64x32, BK=16. Smem tile row-major [row][k], 16B chunk c swizzled
// to c ^ ((row>>1)&3). ldmatrix.x4 yields a0..a3 directly; .x2 yields b0,b1.
// ============================================================================
#define PST 16384                // per-stage: A 8KB + B 8KB

__global__ void __launch_bounds__(256, 2)
gemm_mma(const U32* __restrict__ A, const U32* __restrict__ Wt,
         float* __restrict__ C, int a_heads, int c_heads, int do_rope)
{
    __shared__ __align__(128) char smem[3*PST];
    const U32 sb0 = smem_u32(smem);
    const int t    = threadIdx.x;
    const int lane = t & 31;
    const int wid  = t >> 5;
    const int grp  = lane >> 2;
    const int tig  = lane & 3;
    const int wm   = (wid & 1) * 64;
    const int wn   = (wid >> 1) * 32;
    const int bm   = blockIdx.y * 128;
    const int bn   = blockIdx.x * 128;

    // producer: thread owns row prA (both A and B), k-half prH
    const int prA = t >> 1, prH = t & 1;
    const U32 dsw0 = prA*64 + (((2*prH    ) ^ ((prA>>1)&3)) << 4);
    const U32 dsw1 = prA*64 + (((2*prH + 1) ^ ((prA>>1)&3)) << 4);

    // consumer ldmatrix per-lane address bases
    const int rlA = (lane & 7) | (((lane >> 3) & 1) << 3);   // row within 16
    const int cbA = (lane >> 4) & 1;                          // chunk low bit
    const U32 offA = sb0 + (wm + rlA)*64 + ((cbA ^ ((rlA>>1)&3)) << 4);
    const int rlB = lane & 7;
    const int cbB = (lane >> 3) & 1;
    const U32 offB = sb0 + 8192 + (wn + rlB)*64 + ((cbB ^ ((rlB>>1)&3)) << 4);

    float acc[4][4][4];
    #pragma unroll
    for (int i=0;i<4;++i)
        #pragma unroll
        for (int j=0;j<4;++j)
            #pragma unroll
            for (int r=0;r<4;++r) acc[i][j][r] = 0.0f;

    auto CPA = [&](int kt, int st){
        const U32 sA = sb0 + st*PST;
        const U32 sB = sA + 8192;
        const int e0 = kt*16 + prH*8;
        const U32* pa;
        if (!a_heads) pa = A + (size_t)(bm + prA)*NE + e0;
        else {
            int m = bm + prA, b = m >> 11, s = m & 2047;
            pa = A + ((size_t)((b*16 + (e0 >> 6))*NS + s))*64 + (e0 & 63);
        }
        const U32* pb = Wt + (size_t)(bn + prA)*NE + e0;
        cpa16(sA + dsw0, pa);     cpa16(sA + dsw1, pa + 4);
        cpa16(sB + dsw0, pb);     cpa16(sB + dsw1, pb + 4);
        asm volatile("cp.async.commit_group;" ::: "memory");
    };

    auto MMA = [&](int st){
        const U32 bA = offA + st*PST;
        const U32 bB = offB + st*PST;
        #pragma unroll
        for (int ks = 0; ks < 2; ++ks) {
            U32 af[4][4];
            #pragma unroll
            for (int mf = 0; mf < 4; ++mf)
                ldsm4(af[mf], (bA + mf*1024) ^ (ks << 5));
            U32 bf[4][2];
            #pragma unroll
            for (int nf = 0; nf < 4; ++nf)
                ldsm2(bf[nf], (bB + nf*512) ^ (ks << 5));
            #pragma unroll
            for (int mf = 0; mf < 4; ++mf)
                #pragma unroll
                for (int nf = 0; nf < 4; ++nf)
                    mma8(acc[mf][nf], af[mf], bf[nf]);
        }
    };

    CPA(0, 0); CPA(1, 1);
    for (int kt = 0; kt < 64; ++kt) {
        if (kt < 63) asm volatile("cp.async.wait_group 1;" ::: "memory");
        else         asm volatile("cp.async.wait_group 0;" ::: "memory");
        __syncthreads();
        if (kt < 62) CPA(kt + 2, (kt + 2) % 3);
        MMA(kt % 3);
    }

    // epilogue (+ optional fused RoPE: float2 = one (even,odd) hd pair)
    #pragma unroll
    for (int mf = 0; mf < 4; ++mf) {
        #pragma unroll
        for (int half = 0; half < 2; ++half) {
            int m = bm + wm + mf*16 + grp + half*8;
            #pragma unroll
            for (int nf = 0; nf < 4; ++nf) {
                int n = bn + wn + nf*8 + 2*tig;
                float fx = acc[mf][nf][half*2 + 0];
                float fy = acc[mf][nf][half*2 + 1];
                if (do_rope) {
                    int s = m & 2047;
                    int p = (n & 63) >> 1;
                    float co = g_cos[s*32 + p], sn = g_sin[s*32 + p];
                    float rx = fx*co - fy*sn;
                    float ry = fx*sn + fy*co;
                    fx = rx; fy = ry;
                }
                float2 f = make_float2(fx, fy);
                if (!c_heads) {
                    *(float2*)(C + (size_t)m*NE + n) = f;
                } else {
                    int b = m >> 11, s2 = m & 2047;
                    *(float2*)(C + ((size_t)((b*16 + (n>>6))*NS + s2))*64 + (n & 63)) = f;
                }
            }
        }
    }
}

// ---------------- RoPE table -----------------------------------------------
__global__ void rope_table_kernel()
{
    int idx = blockIdx.x * blockDim.x + threadIdx.x;   // 65536
    if (idx >= NS*32) return;
    int s = idx >> 5, p = idx & 31;
    double invf = 1.0 / pow(10000.0, (double)(2*p) / 64.0);
    double a = (double)s * invf;
    g_cos[idx] = (float)cos(a);
    g_sin[idx] = (float)sin(a);
}

// ============================================================================
// Flash attention v2 (R8, proven): packed-fragment smem layouts. Tile 64x64,
// 128 thr = 4 warps. Epilogue now writes tf32-rounded ctx (for final gemm).
// ============================================================================
__global__ void __launch_bounds__(128)
flash_mma_kernel()
{
    __shared__ __align__(16) char fsm[49152];
    char* Ks = fsm;                 // B-layout, n=kv col, k=hd
    char* Vs = fsm + 16384;         // B-layout, n=hd,    k=kv col
    char* Ps = fsm + 32768;         // A-layout P^T; doubles as Q staging

    const int t    = threadIdx.x;
    const int lane = t & 31;
    const int wid  = t >> 5;
    const int grp  = lane >> 2;          // 0..7
    const int tig  = lane & 3;           // 0..3
    const int wr   = wid * 16;
    const int mfW  = wid;
    const int tigA = tig ^ ((grp >> 1) & 3);
    const int bh   = blockIdx.y;
    const int qb   = (int)gridDim.x - 1 - (int)blockIdx.x;  // heavy first
    const int q0   = qb * 64;

    const float* qp = g_q + (size_t)bh * NS * 64;
    const float* kp = g_k + (size_t)bh * NS * 64;
    const float* vp = g_v + (size_t)bh * NS * 64;

    // ---- stage Q (scaled) into Ps using A-layout ----
    {
        const int r = t >> 1, ksP = t & 1;
        const int mf = r >> 4, g = r & 7, hi = (r >> 3) & 1;
        const int swz = (g >> 1) & 3;
        const float* pq = qp + (size_t)(q0 + r)*64 + ksP*32;
        char* base = Ps + mf*512 + g*64 + hi*4;
        #pragma unroll
        for (int j8 = 0; j8 < 4; ++j8) {
            float4 f0 = *(const float4*)(pq + j8*8);
            float4 f1 = *(const float4*)(pq + j8*8 + 4);
            int ks = ksP*4 + j8;
            float vals[8] = {f0.x,f0.y,f0.z,f0.w,f1.x,f1.y,f1.z,f1.w};
            #pragma unroll
            for (int j = 0; j < 8; ++j) {
                int tg = j & 3, khi = j >> 2;
                *(U32*)(base + ks*2048 + ((tg^swz)<<4) + khi*8) =
                    f2tf(vals[j] * ATT_SCALE);
            }
        }
    }
    __syncthreads();

    // ---- Q fragments -> registers (8 ks x 4 words) ----
    U32 qf[8][4];
    #pragma unroll
    for (int ks = 0; ks < 8; ++ks)
        *(uint4*)qf[ks] =
            *(const uint4*)(Ps + ks*2048 + mfW*512 + grp*64 + (tigA<<4));

    float m_[2], l_[2];
    m_[0] = m_[1] = -1e30f;
    l_[0] = l_[1] = 0.0f;
    float octx[8][4];
    #pragma unroll
    for (int nf=0;nf<8;++nf)
        #pragma unroll
        for (int r=0;r<4;++r) octx[nf][r] = 0.0f;

    for (int kb = 0; kb <= qb; ++kb) {
        const int k0 = kb * 64;
        if (kb) __syncthreads();

        // ---- K producer: B-layout(n=col, k=hd) ----
        #pragma unroll
        for (int it = 0; it < 4; ++it) {
            int idx = it*128 + t;
            int c = idx >> 3, o = idx & 7;
            const float* pk = kp + (size_t)(k0 + c)*64 + o*8;
            float4 f0 = *(const float4*)pk;
            float4 f1 = *(const float4*)(pk+4);
            float vals[8] = {f0.x,f0.y,f0.z,f0.w,f1.x,f1.y,f1.z,f1.w};
            int nf = c >> 3, g = c & 7;
            int swb = ((g>>2)&1) | ((nf&1)<<1);
            char* base = Ks + o*2048 + nf*256 + g*32;
            #pragma unroll
            for (int tg = 0; tg < 4; ++tg) {
                uint2 u;
                u.x = f2tf(vals[tg]);
                u.y = f2tf(vals[tg+4]);
                *(uint2*)(base + ((tg ^ swb ^ (o&3))<<3)) = u;
            }
        }
        // ---- V producer: B-layout(n=hd, k=col) ----
        #pragma unroll
        for (int it = 0; it < 4; ++it) {
            int idx = it*128 + t;
            int rp = idx >> 4, qq = idx & 15;
            int ks = rp >> 2, tg = rp & 3;
            int c = ks*8 + tg;
            const float* pv0 = vp + (size_t)(k0 + c)*64 + qq*4;
            const float* pv1 = vp + (size_t)(k0 + c + 4)*64 + qq*4;
            float4 f0 = *(const float4*)pv0;
            float4 f1 = *(const float4*)pv1;
            float lo4[4] = {f0.x,f0.y,f0.z,f0.w};
            float hi4[4] = {f1.x,f1.y,f1.z,f1.w};
            #pragma unroll
            for (int dn = 0; dn < 4; ++dn) {
                int n = qq*4 + dn, nf = n>>3, g = n&7;
                int swb = ((g>>2)&1) | ((nf&1)<<1);
                uint2 u;
                u.x = f2tf(lo4[dn]);
                u.y = f2tf(hi4[dn]);
                *(uint2*)(Vs + ks*2048 + nf*256 + g*32
                             + ((tg ^ swb ^ (ks&3))<<3)) = u;
            }
        }
        __syncthreads();

        // ---- S = Q @ K^T ----
        float sacc[8][4];
        #pragma unroll
        for (int nf=0;nf<8;++nf)
            #pragma unroll
            for (int r=0;r<4;++r) sacc[nf][r] = 0.0f;
        #pragma unroll
        for (int ks = 0; ks < 8; ++ks) {
            #pragma unroll
            for (int nf = 0; nf < 8; ++nf) {
                int tb = tig ^ (((grp>>2)&1) | ((nf&1)<<1)) ^ (ks&3);
                uint2 bf = *(const uint2*)(Ks + ks*2048 + nf*256
                                              + grp*32 + (tb<<3));
                mma8(sacc[nf], qf[ks], (const U32*)&bf);
            }
        }

        // ---- online softmax; write P^T in A-layout ----
        const bool diag = (kb == qb);
        #pragma unroll
        for (int l = 0; l < 2; ++l) {
            const int rloc = wr + grp + 8*l;
            const int gi   = q0 + rloc;
            float rm = -1e30f;
            #pragma unroll
            for (int nf = 0; nf < 8; ++nf) {
                #pragma unroll
                for (int c = 0; c < 2; ++c) {
                    float s = sacc[nf][2*l + c];
                    if (diag) {
                        int gj = k0 + nf*8 + 2*tig + c;
                        if (gj >= gi && !(gi == 0 && gj == 0)) s = -1e30f;
                    }
                    sacc[nf][2*l + c] = s;
                    rm = fmaxf(rm, s);
                }
            }
            rm = fmaxf(rm, __shfl_xor_sync(0xffffffffu, rm, 1));
            rm = fmaxf(rm, __shfl_xor_sync(0xffffffffu, rm, 2));
            float mnew = fmaxf(m_[l], rm);
            float fac  = __expf(m_[l] - mnew);
            float ps = 0.0f;
            char* pbase = Ps + mfW*512 + grp*64 + l*4;
            const int swzP = (grp >> 1) & 3;
            #pragma unroll
            for (int nf = 0; nf < 8; ++nf) {
                #pragma unroll
                for (int c = 0; c < 2; ++c) {
                    float p = __expf(sacc[nf][2*l + c] - mnew);
                    int j = 2*tig + c;
                    int tg = j & 3, khi = j >> 2;
                    *(U32*)(pbase + nf*2048 + ((tg^swzP)<<4) + khi*8) = f2tf(p);
                    ps += p;
                }
            }
            ps += __shfl_xor_sync(0xffffffffu, ps, 1);
            ps += __shfl_xor_sync(0xffffffffu, ps, 2);
            l_[l] = l_[l]*fac + ps;
            m_[l] = mnew;
            #pragma unroll
            for (int nf = 0; nf < 8; ++nf) {
                octx[nf][2*l + 0] *= fac;
                octx[nf][2*l + 1] *= fac;
            }
        }
        __syncwarp();

        // ---- ctx += P @ V ----
        #pragma unroll
        for (int ks = 0; ks < 8; ++ks) {
            uint4 af = *(const uint4*)(Ps + ks*2048 + mfW*512
                                          + grp*64 + (tigA<<4));
            #pragma unroll
            for (int nf = 0; nf < 8; ++nf) {
                int tb = tig ^ (((grp>>2)&1) | ((nf&1)<<1)) ^ (ks&3);
                uint2 bf = *(const uint2*)(Vs + ks*2048 + nf*256
                                              + grp*32 + (tb<<3));
                mma8(octx[nf], (const U32*)&af, (const U32*)&bf);
            }
        }
    }

    // ---- normalize + write ctx tf32-rounded (head-major) ----
    U32* op = (U32*)(g_ctx + (size_t)bh * NS * 64);
    #pragma unroll
    for (int l = 0; l < 2; ++l) {
        const int r  = q0 + wr + grp + 8*l;
        const float inv = 1.0f / l_[l];
        #pragma unroll
        for (int nf = 0; nf < 8; ++nf) {
            uint2 u;
            u.x = f2tf(octx[nf][2*l + 0] * inv);
            u.y = f2tf(octx[nf][2*l + 1] * inv);
            *(uint2*)(op + (size_t)r*64 + nf*8 + 2*tig) = u;
        }
    }
}

// ---------------------------------------------------------------------------
extern "C" void kernel_launch(void* const* d_in, const int* in_sizes, int n_in,
                              void* d_out, int out_size)
{
    const float* q  = (const float*)d_in[0];
    const float* k  = (const float*)d_in[1];
    const float* v  = (const float*)d_in[2];
    const float* Wq = (const float*)d_in[3];
    const float* Wk = (const float*)d_in[4];
    const float* Wv = (const float*)d_in[5];
    const float* Wo = (const float*)d_in[6];
    float* out = (float*)d_out;

    float *pq, *pk, *pv, *pctx;
    cudaGetSymbolAddress((void**)&pq,   g_q);
    cudaGetSymbolAddress((void**)&pk,   g_k);
    cudaGetSymbolAddress((void**)&pv,   g_v);
    cudaGetSymbolAddress((void**)&pctx, g_ctx);
    U32 *pqc, *pkc, *pvc, *pwq, *pwk, *pwv, *pwo;
    cudaGetSymbolAddress((void**)&pqc, g_qc);
    cudaGetSymbolAddress((void**)&pkc, g_kc);
    cudaGetSymbolAddress((void**)&pvc, g_vc);
    cudaGetSymbolAddress((void**)&pwq, g_wqc);
    cudaGetSymbolAddress((void**)&pwk, g_wkc);
    cudaGetSymbolAddress((void**)&pwv, g_wvc);
    cudaGetSymbolAddress((void**)&pwo, g_woc);

    rope_table_kernel<<<256, 256>>>();
    prep_kernel<<<(3*Q4 + 4*W4)/256, 256>>>((const float4*)q, (const float4*)k,
        (const float4*)v, (const float4*)Wq, (const float4*)Wk,
        (const float4*)Wv, (const float4*)Wo);

    dim3 gg(NE/128, NM/128);               // (8, 32)
    gemm_mma<<<gg, 256>>>(pqc, pwq, pq, 0, 1, 1);   // Q proj + RoPE
    gemm_mma<<<gg, 256>>>(pkc, pwk, pk, 0, 1, 1);   // K proj + RoPE
    gemm_mma<<<gg, 256>>>(pvc, pwv, pv, 0, 1, 0);   // V proj

    dim3 fg(NS/64, NB*NH);                 // (32, 32)
    flash_mma_kernel<<<fg, 128>>>();

    gemm_mma<<<gg, 256>>>((const U32*)pctx, pwo, out, 1, 0, 0);  // output proj
}

// round 11
// speedup vs baseline: 1.6556x; 1.1623x over previous
#include <cuda_runtime.h>
#include <math.h>

typedef unsigned long long ULL;
typedef unsigned int U32;

#define NB 2
#define NS 2048
#define NE 1024
#define NH 16
#define NHD 64
#define NM 4096                  // NB*NS
#define ATT_SCALE (1.0f/32.0f)   // 1/sqrt(1024), exact power of two

// ---------------- scratch (device globals; no allocation allowed) ----------
__device__ float g_q[NB*NH*NS*NHD];    // head-major: [b*16+h][s][hd]
__device__ float g_k[NB*NH*NS*NHD];
__device__ float g_v[NB*NH*NS*NHD];
__device__ float g_ctx[NB*NH*NS*NHD];  // written tf32-rounded by flash
__device__ float g_cos[NS*32];
__device__ float g_sin[NS*32];
// pre-converted tf32-bit operands
__device__ U32 g_qc[NM*NE];
__device__ U32 g_kc[NM*NE];
__device__ U32 g_vc[NM*NE];
__device__ U32 g_wqc[NE*NE];
__device__ U32 g_wkc[NE*NE];
__device__ U32 g_wvc[NE*NE];
__device__ U32 g_woc[NE*NE];
// K/V pre-packed into flash B-layout smem images: [bh][kb][4096 U32]
__device__ U32 g_kt[NB*NH*32*4096];
__device__ U32 g_vt[NB*NH*32*4096];

// ---------------- helpers ---------------------------------------------------
__device__ __forceinline__ U32 f2tf(float x){
    U32 u; asm("cvt.rn.tf32.f32 %0, %1;" : "=r"(u) : "f"(x)); return u;
}
__device__ __forceinline__ void mma8(float* c, const U32* a, const U32* b){
    asm volatile("mma.sync.aligned.m16n8k8.row.col.f32.tf32.tf32.f32 "
        "{%0,%1,%2,%3}, {%4,%5,%6,%7}, {%8,%9}, {%0,%1,%2,%3};"
        : "+f"(c[0]), "+f"(c[1]), "+f"(c[2]), "+f"(c[3])
        : "r"(a[0]), "r"(a[1]), "r"(a[2]), "r"(a[3]), "r"(b[0]), "r"(b[1]));
}
__device__ __forceinline__ U32 smem_u32(const void* p){
    U32 a;
    asm("{ .reg .u64 t; cvta.to.shared.u64 t, %1; cvt.u32.u64 %0, t; }"
        : "=r"(a) : "l"(p));
    return a;
}
__device__ __forceinline__ void ldsm4(U32* r, U32 a){
    asm volatile("ldmatrix.sync.aligned.m8n8.x4.shared.b16 {%0,%1,%2,%3}, [%4];"
        : "=r"(r[0]), "=r"(r[1]), "=r"(r[2]), "=r"(r[3]) : "r"(a));
}
__device__ __forceinline__ void ldsm2(U32* r, U32 a){
    asm volatile("ldmatrix.sync.aligned.m8n8.x2.shared.b16 {%0,%1}, [%2];"
        : "=r"(r[0]), "=r"(r[1]) : "r"(a));
}
__device__ __forceinline__ void cpa16(U32 dst, const void* src){
    asm volatile("cp.async.cg.shared.global [%0], [%1], 16;"
                 :: "r"(dst), "l"(src) : "memory");
}

// ---------------- prep: fp32 -> tf32 bits (RN) ------------------------------
#define Q4 (NM*NE/4)
#define W4 (NE*NE/4)
__global__ void prep_kernel(const float4* __restrict__ q, const float4* __restrict__ k,
                            const float4* __restrict__ v, const float4* __restrict__ wq,
                            const float4* __restrict__ wk, const float4* __restrict__ wv,
                            const float4* __restrict__ wo)
{
    int i = blockIdx.x * blockDim.x + threadIdx.x;
    const float4* s; uint4* d;
    if      (i <   Q4) { s = q + i;        d = (uint4*)g_qc + i; }
    else if (i < 2*Q4) { s = k + (i-Q4);   d = (uint4*)g_kc + (i-Q4); }
    else if (i < 3*Q4) { s = v + (i-2*Q4); d = (uint4*)g_vc + (i-2*Q4); }
    else {
        int j = i - 3*Q4, w = j / W4, o = j - w*W4;
        const float4* ws[4] = {wq, wk, wv, wo};
        uint4* wd[4] = {(uint4*)g_wqc, (uint4*)g_wkc, (uint4*)g_wvc, (uint4*)g_woc};
        s = ws[w] + o; d = wd[w] + o;
    }
    float4 f = *s;
    *d = make_uint4(f2tf(f.x), f2tf(f.y), f2tf(f.z), f2tf(f.w));
}

// ---------------- kvprep: pack K/V tiles into flash B-layout ----------------
// grid (32 kb, 32 bh, 2 mode); 256 thr. Byte-identical to the old in-kernel
// producers:
//  K (mode 0): group(o,nf,g,tg): addr o*2048+nf*256+g*32+((tg^swb^(o&3))<<3)
//              = { K[c=nf*8+g][o*8+tg], K[c][o*8+tg+4] }
//  V (mode 1): group(ks,nf,g,tg): addr ks*2048+nf*256+g*32+((tg^swb^(ks&3))<<3)
//              = { V[ks*8+tg][n=nf*8+g], V[ks*8+tg+4][n] }
__global__ void __launch_bounds__(256)
kvprep_kernel()
{
    __shared__ float sm[64][68];
    const int kb = blockIdx.x, bh = blockIdx.y, mode = blockIdx.z;
    const int t  = threadIdx.x;
    const float* src = (mode ? g_v : g_k) + (size_t)bh*NS*64 + (size_t)kb*64*64;
    U32* dst = (mode ? g_vt : g_kt) + ((size_t)bh*32 + kb)*4096;

    #pragma unroll
    for (int it = 0; it < 4; ++it) {
        int i4 = it*256 + t;             // 1024 float4
        int row = i4 >> 4, c4 = i4 & 15;
        float4 f = *(const float4*)(src + row*64 + c4*4);
        sm[row][c4*4+0]=f.x; sm[row][c4*4+1]=f.y;
        sm[row][c4*4+2]=f.z; sm[row][c4*4+3]=f.w;
    }
    __syncthreads();

    #pragma unroll
    for (int it = 0; it < 4; ++it) {
        int ch = it*256 + t;             // 1024 x 16B chunks
        int off = ch * 16;
        int o  = off >> 11;
        int r1 = off & 2047;
        int nf = r1 >> 8;
        int g  = (r1 >> 5) & 7;
        int w0 = (off & 31) >> 3;        // 0 or 2
        int swb = ((g>>2)&1) | ((nf&1)<<1);
        uint4 u;
        if (mode == 0) {
            int c = nf*8 + g;
            int tg0 = w0 ^ swb ^ (o&3), tg1 = (w0+1) ^ swb ^ (o&3);
            u.x = f2tf(sm[c][o*8 + tg0]);
            u.y = f2tf(sm[c][o*8 + tg0 + 4]);
            u.z = f2tf(sm[c][o*8 + tg1]);
            u.w = f2tf(sm[c][o*8 + tg1 + 4]);
        } else {
            int n = nf*8 + g;
            int tg0 = w0 ^ swb ^ (o&3), tg1 = (w0+1) ^ swb ^ (o&3);
            u.x = f2tf(sm[o*8 + tg0][n]);
            u.y = f2tf(sm[o*8 + tg0 + 4][n]);
            u.z = f2tf(sm[o*8 + tg1][n]);
            u.w = f2tf(sm[o*8 + tg1 + 4][n]);
        }
        *(uint4*)(dst + ch*4) = u;
    }
}

// ============================================================================
// Projection GEMM v5 (R10, proven): cp.async 3-stage + ldmatrix.
// ============================================================================
#define PST 16384

__global__ void __launch_bounds__(256, 2)
gemm_mma(const U32* __restrict__ A, const U32* __restrict__ Wt,
         float* __restrict__ C, int a_heads, int c_heads, int do_rope)
{
    __shared__ __align__(128) char smem[3*PST];
    const U32 sb0 = smem_u32(smem);
    const int t    = threadIdx.x;
    const int lane = t & 31;
    const int wid  = t >> 5;
    const int grp  = lane >> 2;
    const int tig  = lane & 3;
    const int wm   = (wid & 1) * 64;
    const int wn   = (wid >> 1) * 32;
    const int bm   = blockIdx.y * 128;
    const int bn   = blockIdx.x * 128;

    const int prA = t >> 1, prH = t & 1;
    const U32 dsw0 = prA*64 + (((2*prH    ) ^ ((prA>>1)&3)) << 4);
    const U32 dsw1 = prA*64 + (((2*prH + 1) ^ ((prA>>1)&3)) << 4);

    const int rlA = (lane & 7) | (((lane >> 3) & 1) << 3);
    const int cbA = (lane >> 4) & 1;
    const U32 offA = sb0 + (wm + rlA)*64 + ((cbA ^ ((rlA>>1)&3)) << 4);
    const int rlB = lane & 7;
    const int cbB = (lane >> 3) & 1;
    const U32 offB = sb0 + 8192 + (wn + rlB)*64 + ((cbB ^ ((rlB>>1)&3)) << 4);

    float acc[4][4][4];
    #pragma unroll
    for (int i=0;i<4;++i)
        #pragma unroll
        for (int j=0;j<4;++j)
            #pragma unroll
            for (int r=0;r<4;++r) acc[i][j][r] = 0.0f;

    auto CPA = [&](int kt, int st){
        const U32 sA = sb0 + st*PST;
        const U32 sB = sA + 8192;
        const int e0 = kt*16 + prH*8;
        const U32* pa;
        if (!a_heads) pa = A + (size_t)(bm + prA)*NE + e0;
        else {
            int m = bm + prA, b = m >> 11, s = m & 2047;
            pa = A + ((size_t)((b*16 + (e0 >> 6))*NS + s))*64 + (e0 & 63);
        }
        const U32* pb = Wt + (size_t)(bn + prA)*NE + e0;
        cpa16(sA + dsw0, pa);     cpa16(sA + dsw1, pa + 4);
        cpa16(sB + dsw0, pb);     cpa16(sB + dsw1, pb + 4);
        asm volatile("cp.async.commit_group;" ::: "memory");
    };

    auto MMA = [&](int st){
        const U32 bA = offA + st*PST;
        const U32 bB = offB + st*PST;
        #pragma unroll
        for (int ks = 0; ks < 2; ++ks) {
            U32 af[4][4];
            #pragma unroll
            for (int mf = 0; mf < 4; ++mf)
                ldsm4(af[mf], (bA + mf*1024) ^ (ks << 5));
            U32 bf[4][2];
            #pragma unroll
            for (int nf = 0; nf < 4; ++nf)
                ldsm2(bf[nf], (bB + nf*512) ^ (ks << 5));
            #pragma unroll
            for (int mf = 0; mf < 4; ++mf)
                #pragma unroll
                for (int nf = 0; nf < 4; ++nf)
                    mma8(acc[mf][nf], af[mf], bf[nf]);
        }
    };

    CPA(0, 0); CPA(1, 1);
    for (int kt = 0; kt < 64; ++kt) {
        if (kt < 63) asm volatile("cp.async.wait_group 1;" ::: "memory");
        else         asm volatile("cp.async.wait_group 0;" ::: "memory");
        __syncthreads();
        if (kt < 62) CPA(kt + 2, (kt + 2) % 3);
        MMA(kt % 3);
    }

    #pragma unroll
    for (int mf = 0; mf < 4; ++mf) {
        #pragma unroll
        for (int half = 0; half < 2; ++half) {
            int m = bm + wm + mf*16 + grp + half*8;
            #pragma unroll
            for (int nf = 0; nf < 4; ++nf) {
                int n = bn + wn + nf*8 + 2*tig;
                float fx = acc[mf][nf][half*2 + 0];
                float fy = acc[mf][nf][half*2 + 1];
                if (do_rope) {
                    int s = m & 2047;
                    int p = (n & 63) >> 1;
                    float co = g_cos[s*32 + p], sn = g_sin[s*32 + p];
                    float rx = fx*co - fy*sn;
                    float ry = fx*sn + fy*co;
                    fx = rx; fy = ry;
                }
                float2 f = make_float2(fx, fy);
                if (!c_heads) {
                    *(float2*)(C + (size_t)m*NE + n) = f;
                } else {
                    int b = m >> 11, s2 = m & 2047;
                    *(float2*)(C + ((size_t)((b*16 + (n>>6))*NS + s2))*64 + (n & 63)) = f;
                }
            }
        }
    }
}

// ---------------- RoPE table -----------------------------------------------
__global__ void rope_table_kernel()
{
    int idx = blockIdx.x * blockDim.x + threadIdx.x;
    if (idx >= NS*32) return;
    int s = idx >> 5, p = idx & 31;
    double invf = 1.0 / pow(10000.0, (double)(2*p) / 64.0);
    double a = (double)s * invf;
    g_cos[idx] = (float)cos(a);
    g_sin[idx] = (float)sin(a);
}

// ============================================================================
// Flash attention v3: K/V tiles streamed via cp.async from pre-packed
// g_kt/g_vt (B-layout), 2-stage double buffer. Tile 64x64, 128 thr = 4 warps.
// Dynamic smem: Ks[2][16KB] + Vs[2][16KB] + Ps[16KB] = 80KB.
// ============================================================================
#define FLS_BYTES (5*16384)

__global__ void __launch_bounds__(128)
flash_mma_kernel()
{
    extern __shared__ __align__(128) char fsm[];
    char* Ks = fsm;                      // 2 stages x 16KB
    char* Vs = fsm + 32768;              // 2 stages x 16KB
    char* Ps = fsm + 65536;              // A-layout P^T; doubles as Q staging

    const int t    = threadIdx.x;
    const int lane = t & 31;
    const int wid  = t >> 5;
    const int grp  = lane >> 2;
    const int tig  = lane & 3;
    const int wr   = wid * 16;
    const int mfW  = wid;
    const int tigA = tig ^ ((grp >> 1) & 3);
    const int bh   = blockIdx.y;
    const int qb   = (int)gridDim.x - 1 - (int)blockIdx.x;  // heavy first
    const int q0   = qb * 64;

    const float* qp = g_q + (size_t)bh * NS * 64;
    const U32* ktp = g_kt + (size_t)bh * 32 * 4096;
    const U32* vtp = g_vt + (size_t)bh * 32 * 4096;
    const U32 sbK = smem_u32(Ks);
    const U32 sbV = smem_u32(Vs);

    auto CPAKV = [&](int kb, int st){
        const U32 dK = sbK + st*16384;
        const U32 dV = sbV + st*16384;
        const U32* sK = ktp + (size_t)kb*4096;
        const U32* sV = vtp + (size_t)kb*4096;
        #pragma unroll
        for (int i = 0; i < 8; ++i) {
            int c = i*128 + t;
            cpa16(dK + c*16, sK + c*4);
            cpa16(dV + c*16, sV + c*4);
        }
        asm volatile("cp.async.commit_group;" ::: "memory");
    };

    // ---- stage Q (scaled) into Ps using A-layout ----
    {
        const int r = t >> 1, ksP = t & 1;
        const int mf = r >> 4, g = r & 7, hi = (r >> 3) & 1;
        const int swz = (g >> 1) & 3;
        const float* pq = qp + (size_t)(q0 + r)*64 + ksP*32;
        char* base = Ps + mf*512 + g*64 + hi*4;
        #pragma unroll
        for (int j8 = 0; j8 < 4; ++j8) {
            float4 f0 = *(const float4*)(pq + j8*8);
            float4 f1 = *(const float4*)(pq + j8*8 + 4);
            int ks = ksP*4 + j8;
            float vals[8] = {f0.x,f0.y,f0.z,f0.w,f1.x,f1.y,f1.z,f1.w};
            #pragma unroll
            for (int j = 0; j < 8; ++j) {
                int tg = j & 3, khi = j >> 2;
                *(U32*)(base + ks*2048 + ((tg^swz)<<4) + khi*8) =
                    f2tf(vals[j] * ATT_SCALE);
            }
        }
    }
    CPAKV(0, 0);                         // prefetch first K/V tile
    __syncthreads();

    // ---- Q fragments -> registers ----
    U32 qf[8][4];
    #pragma unroll
    for (int ks = 0; ks < 8; ++ks)
        *(uint4*)qf[ks] =
            *(const uint4*)(Ps + ks*2048 + mfW*512 + grp*64 + (tigA<<4));

    float m_[2], l_[2];
    m_[0] = m_[1] = -1e30f;
    l_[0] = l_[1] = 0.0f;
    float octx[8][4];
    #pragma unroll
    for (int nf=0;nf<8;++nf)
        #pragma unroll
        for (int r=0;r<4;++r) octx[nf][r] = 0.0f;

    for (int kb = 0; kb <= qb; ++kb) {
        const int st = kb & 1;
        if (kb < qb) CPAKV(kb + 1, (kb + 1) & 1);
        if (kb < qb) asm volatile("cp.async.wait_group 1;" ::: "memory");
        else         asm volatile("cp.async.wait_group 0;" ::: "memory");
        __syncthreads();                 // K/V tile kb ready; Ps safe to reuse

        const int k0 = kb * 64;
        char* Kc = Ks + st*16384;
        char* Vc = Vs + st*16384;

        // ---- S = Q @ K^T ----
        float sacc[8][4];
        #pragma unroll
        for (int nf=0;nf<8;++nf)
            #pragma unroll
            for (int r=0;r<4;++r) sacc[nf][r] = 0.0f;
        #pragma unroll
        for (int ks = 0; ks < 8; ++ks) {
            #pragma unroll
            for (int nf = 0; nf < 8; ++nf) {
                int tb = tig ^ (((grp>>2)&1) | ((nf&1)<<1)) ^ (ks&3);
                uint2 bf = *(const uint2*)(Kc + ks*2048 + nf*256
                                              + grp*32 + (tb<<3));
                mma8(sacc[nf], qf[ks], (const U32*)&bf);
            }
        }

        // ---- online softmax; write P^T in A-layout ----
        const bool diag = (kb == qb);
        #pragma unroll
        for (int l = 0; l < 2; ++l) {
            const int rloc = wr + grp + 8*l;
            const int gi   = q0 + rloc;
            float rm = -1e30f;
            #pragma unroll
            for (int nf = 0; nf < 8; ++nf) {
                #pragma unroll
                for (int c = 0; c < 2; ++c) {
                    float s = sacc[nf][2*l + c];
                    if (diag) {
                        int gj = k0 + nf*8 + 2*tig + c;
                        if (gj >= gi && !(gi == 0 && gj == 0)) s = -1e30f;
                    }
                    sacc[nf][2*l + c] = s;
                    rm = fmaxf(rm, s);
                }
            }
            rm = fmaxf(rm, __shfl_xor_sync(0xffffffffu, rm, 1));
            rm = fmaxf(rm, __shfl_xor_sync(0xffffffffu, rm, 2));
            float mnew = fmaxf(m_[l], rm);
            float fac  = __expf(m_[l] - mnew);
            float ps = 0.0f;
            char* pbase = Ps + mfW*512 + grp*64 + l*4;
            const int swzP = (grp >> 1) & 3;
            #pragma unroll
            for (int nf = 0; nf < 8; ++nf) {
                #pragma unroll
                for (int c = 0; c < 2; ++c) {
                    float p = __expf(sacc[nf][2*l + c] - mnew);
                    int j = 2*tig + c;
                    int tg = j & 3, khi = j >> 2;
                    *(U32*)(pbase + nf*2048 + ((tg^swzP)<<4) + khi*8) = f2tf(p);
                    ps += p;
                }
            }
            ps += __shfl_xor_sync(0xffffffffu, ps, 1);
            ps += __shfl_xor_sync(0xffffffffu, ps, 2);
            l_[l] = l_[l]*fac + ps;
            m_[l] = mnew;
            #pragma unroll
            for (int nf = 0; nf < 8; ++nf) {
                octx[nf][2*l + 0] *= fac;
                octx[nf][2*l + 1] *= fac;
            }
        }
        __syncwarp();                    // P^T region is warp-private

        // ---- ctx += P @ V ----
        #pragma unroll
        for (int ks = 0; ks < 8; ++ks) {
            uint4 af = *(const uint4*)(Ps + ks*2048 + mfW*512
                                          + grp*64 + (tigA<<4));
            #pragma unroll
            for (int nf = 0; nf < 8; ++nf) {
                int tb = tig ^ (((grp>>2)&1) | ((nf&1)<<1)) ^ (ks&3);
                uint2 bf = *(const uint2*)(Vc + ks*2048 + nf*256
                                              + grp*32 + (tb<<3));
                mma8(octx[nf], (const U32*)&af, (const U32*)&bf);
            }
        }
        __syncthreads();                 // all warps done with buffer st
    }

    // ---- normalize + write ctx tf32-rounded (head-major) ----
    U32* op = (U32*)(g_ctx + (size_t)bh * NS * 64);
    #pragma unroll
    for (int l = 0; l < 2; ++l) {
        const int r  = q0 + wr + grp + 8*l;
        const float inv = 1.0f / l_[l];
        #pragma unroll
        for (int nf = 0; nf < 8; ++nf) {
            uint2 u;
            u.x = f2tf(octx[nf][2*l + 0] * inv);
            u.y = f2tf(octx[nf][2*l + 1] * inv);
            *(uint2*)(op + (size_t)r*64 + nf*8 + 2*tig) = u;
        }
    }
}

// ---------------------------------------------------------------------------
extern "C" void kernel_launch(void* const* d_in, const int* in_sizes, int n_in,
                              void* d_out, int out_size)
{
    const float* q  = (const float*)d_in[0];
    const float* k  = (const float*)d_in[1];
    const float* v  = (const float*)d_in[2];
    const float* Wq = (const float*)d_in[3];
    const float* Wk = (const float*)d_in[4];
    const float* Wv = (const float*)d_in[5];
    const float* Wo = (const float*)d_in[6];
    float* out = (float*)d_out;

    float *pq, *pk, *pv, *pctx;
    cudaGetSymbolAddress((void**)&pq,   g_q);
    cudaGetSymbolAddress((void**)&pk,   g_k);
    cudaGetSymbolAddress((void**)&pv,   g_v);
    cudaGetSymbolAddress((void**)&pctx, g_ctx);
    U32 *pqc, *pkc, *pvc, *pwq, *pwk, *pwv, *pwo;
    cudaGetSymbolAddress((void**)&pqc, g_qc);
    cudaGetSymbolAddress((void**)&pkc, g_kc);
    cudaGetSymbolAddress((void**)&pvc, g_vc);
    cudaGetSymbolAddress((void**)&pwq, g_wqc);
    cudaGetSymbolAddress((void**)&pwk, g_wkc);
    cudaGetSymbolAddress((void**)&pwv, g_wvc);
    cudaGetSymbolAddress((void**)&pwo, g_woc);

    cudaFuncSetAttribute(flash_mma_kernel,
                         cudaFuncAttributeMaxDynamicSharedMemorySize,
                         FLS_BYTES);

    rope_table_kernel<<<256, 256>>>();
    prep_kernel<<<(3*Q4 + 4*W4)/256, 256>>>((const float4*)q, (const float4*)k,
        (const float4*)v, (const float4*)Wq, (const float4*)Wk,
        (const float4*)Wv, (const float4*)Wo);

    dim3 gg(NE/128, NM/128);               // (8, 32)
    gemm_mma<<<gg, 256>>>(pqc, pwq, pq, 0, 1, 1);   // Q proj + RoPE
    gemm_mma<<<gg, 256>>>(pkc, pwk, pk, 0, 1, 1);   // K proj + RoPE
    gemm_mma<<<gg, 256>>>(pvc, pwv, pv, 0, 1, 0);   // V proj

    dim3 kvg(32, NB*NH, 2);
    kvprep_kernel<<<kvg, 256>>>();         // pack K/V into B-layout tiles

    dim3 fg(NS/64, NB*NH);                 // (32, 32)
    flash_mma_kernel<<<fg, 128, FLS_BYTES>>>();

    gemm_mma<<<gg, 256>>>((const U32*)pctx, pwo, out, 1, 0, 0);  // output proj
}